// round 9
// baseline (speedup 1.0000x reference)
#include <cuda_runtime.h>
#include <cuda_bf16.h>
#include <cstdint>
#include <math.h>

// Problem constants (fixed by setup_inputs)
#define NPIX 32768      // B*H*W = 8*64*64
#define PP   4096       // H*W
#define CC   2048       // channels (GEMM K)
#define DD   256        // projection dim (GEMM N)
#define NMEM 256        // memory bank rows
#define NS   64         // NUM_SAMPLES

// GEMM tiling
#define BK     32                  // K per stage
#define KT     (CC / BK)           // 64 k-iterations
#define STG_A  0                   // bf16 A [32 k][128 m] = 8KB
#define STG_BH 8192                // bf16 Bh [256 n][32 k] = 16KB
#define STG_BL 24576               // bf16 Bl = 16KB
#define STGB   40960
#define SM_MMA (3 * STGB)          // 122880 dynamic smem

#define ZKC    16                  // zsel k-chunks (128 channels each)

typedef unsigned long long ull;

// ---------------- device scratch (static: no allocations allowed) ----------
__device__ __align__(16) __nv_bfloat16 g_bh[(size_t)DD * CC];     // W hi, [n=d][k=c]
__device__ __align__(16) __nv_bfloat16 g_bl[(size_t)DD * CC];     // W lo
__device__ float g_psum[256 * DD];              // per-CTA column sums
__device__ float g_psq[256 * DD];               // per-CTA column sumsq
__device__ int   g_sel_idx[128];                // fg[0..63], bg[64..127]
__device__ float g_sel_valid[128];
__device__ float g_zpart[ZKC][128 * DD];        // per-kchunk partial z at selected rows
__device__ float g_nf[128 * DD];                // normalized selected features
__device__ float g_mn[2 * NMEM];                // memory-bank inverse norms
__device__ float g_pe[64], g_ne[64];            // per-task exp sums

// ---------------- PTX helpers (sm_100-base legal) ----------------
__device__ __forceinline__ uint32_t smem_u32(const void* p) {
    uint32_t a;
    asm("{ .reg .u64 t; cvta.to.shared.u64 t, %1; cvt.u32.u64 %0, t; }"
        : "=r"(a) : "l"(p));
    return a;
}

#define CP16(dst, src) \
    asm volatile("{ .reg .u64 p; cvta.to.global.u64 p, %1; " \
                 "cp.async.cg.shared.global [%0], [p], 16; }" \
                 :: "r"(dst), "l"(src))

#define CP_COMMIT() asm volatile("cp.async.commit_group;" ::: "memory")

#define LDSM4(r0, r1, r2, r3, addr) \
    asm volatile("ldmatrix.sync.aligned.m8n8.x4.shared.b16 {%0,%1,%2,%3}, [%4];" \
                 : "=r"(r0), "=r"(r1), "=r"(r2), "=r"(r3) : "r"(addr))

#define LDSM4T(r0, r1, r2, r3, addr) \
    asm volatile("ldmatrix.sync.aligned.m8n8.x4.trans.shared.b16 {%0,%1,%2,%3}, [%4];" \
                 : "=r"(r0), "=r"(r1), "=r"(r2), "=r"(r3) : "r"(addr))

#define MMA_BF16(c, a, b0, b1) \
    asm volatile("mma.sync.aligned.m16n8k16.row.col.f32.bf16.bf16.f32 " \
                 "{%0,%1,%2,%3}, {%4,%5,%6,%7}, {%8,%9}, {%0,%1,%2,%3};" \
                 : "+f"((c)[0]), "+f"((c)[1]), "+f"((c)[2]), "+f"((c)[3]) \
                 : "r"((a)[0]), "r"((a)[1]), "r"((a)[2]), "r"((a)[3]), \
                   "r"(b0), "r"(b1))

// B-tile swizzle (rows of 64B, 16B chunks c 0..3) — proven in R4
__device__ __forceinline__ uint32_t swzB(int r, int c) {
    return (uint32_t)(r * 64 + 16 * (c ^ ((r >> 1) & 3)));
}
// A-tile swizzle: [k rows][128 m bf16 = 256B = 16 chunks]
__device__ __forceinline__ uint32_t swzA(int k, int mc) {
    return (uint32_t)(k * 256 + 16 * (mc ^ (k & 15)));
}

// =====================================================================
// Kernel 1: hard-sample mining. block 0 -> fg (label==1), block 1 -> bg.
// Iterative block-argmax (64 rounds) replicating jax.lax.top_k exactly.
// =====================================================================
__global__ void k_select(const float* __restrict__ pred_ori,
                         const float* __restrict__ pred_aug,
                         const float* __restrict__ unc,
                         const int*   __restrict__ labels)
{
    const int cls = blockIdx.x;          // 0: fg, 1: bg
    const int tid = threadIdx.x;         // 1024 threads
    const int want = cls ? 0 : 1;

    float sc[32];
    #pragma unroll
    for (int i = 0; i < 32; i++) {
        int n = tid + (i << 10);
        int b = n >> 12, p = n & 4095;
        const float* po = pred_ori + (size_t)b * 2 * PP + p;
        const float* pa = pred_aug + (size_t)b * 2 * PP + p;
        int io = po[PP] > po[0];
        int ia = pa[PP] > pa[0];
        float u = unc[n];
        bool ok = (io == ia) && (u > 0.5f) && (labels[n] == want);
        sc[i] = ok ? u : -1e9f;
    }

    float bv = -INFINITY; int bi = -1;
    #pragma unroll
    for (int i = 0; i < 32; i++) {
        int n = tid + (i << 10);
        if (sc[i] > bv || (sc[i] == bv && n < bi)) { bv = sc[i]; bi = n; }
    }

    __shared__ float wv[32];
    __shared__ int   wi[32];
    __shared__ int   winner;

    for (int it = 0; it < NS; it++) {
        float v = bv; int ix = bi;
        #pragma unroll
        for (int o = 16; o; o >>= 1) {
            float ov = __shfl_down_sync(0xffffffffu, v, o);
            int   oi = __shfl_down_sync(0xffffffffu, ix, o);
            if (ov > v || (ov == v && oi < ix)) { v = ov; ix = oi; }
        }
        if ((tid & 31) == 0) { wv[tid >> 5] = v; wi[tid >> 5] = ix; }
        __syncthreads();
        if (tid < 32) {
            v = wv[tid]; ix = wi[tid];
            #pragma unroll
            for (int o = 16; o; o >>= 1) {
                float ov = __shfl_down_sync(0xffffffffu, v, o);
                int   oi = __shfl_down_sync(0xffffffffu, ix, o);
                if (ov > v || (ov == v && oi < ix)) { v = ov; ix = oi; }
            }
            if (tid == 0) {
                winner = ix;
                g_sel_idx[cls * NS + it]   = ix;
                g_sel_valid[cls * NS + it] = (v > -5e8f) ? 1.0f : 0.0f;
            }
        }
        __syncthreads();
        int wn = winner;
        if ((wn & 1023) == tid) {
            sc[wn >> 10] = -INFINITY;
            bv = -INFINITY; bi = -1;
            #pragma unroll
            for (int i = 0; i < 32; i++) {
                int n = tid + (i << 10);
                if (sc[i] > bv || (sc[i] == bv && n < bi)) { bv = sc[i]; bi = n; }
            }
        }
        __syncthreads();
    }
}

// =====================================================================
// Kernel 2: W -> bf16 hi/lo, transposed to [n=d][k=c] (K-major).
// conv_b omitted: cancels exactly in BatchNorm.
// =====================================================================
__global__ void __launch_bounds__(256) k_wconv(const float* __restrict__ Wt)
{
    __shared__ float s[32][33];
    const int bid = blockIdx.x;         // 512 blocks
    const int tid = threadIdx.x;
    const int li = tid >> 5;            // 0..7
    const int lj = tid & 31;
    const int d0 = (bid & 7) << 5, c0 = (bid >> 3) << 5;

    #pragma unroll
    for (int i4 = 0; i4 < 4; i4++) {
        int i = li + i4 * 8;
        s[i][lj] = Wt[(size_t)(c0 + i) * DD + d0 + lj];
    }
    __syncthreads();
    #pragma unroll
    for (int i4 = 0; i4 < 4; i4++) {
        int r = li + i4 * 8;            // d-local
        float f = s[lj][r];             // W[c0+lj][d0+r]
        __nv_bfloat16 h = __float2bfloat16(f);
        __nv_bfloat16 l = __float2bfloat16(f - __bfloat162float(h));
        g_bh[(size_t)(d0 + r) * CC + c0 + lj] = h;
        g_bl[(size_t)(d0 + r) * CC + c0 + lj] = l;
    }
}

// =====================================================================
// Kernel 3 (launched 3rd): exact fp32 z partials for the 128 selected
// rows. 512 blocks = 32 row-groups (4 rows) x 16 k-chunks (128 ch).
// =====================================================================
__global__ void __launch_bounds__(256) k_zsel(const float* __restrict__ F,
                                              const float* __restrict__ Wt)
{
    __shared__ float f[4][128];
    const int rg  = blockIdx.x >> 4;    // 0..31
    const int kc  = blockIdx.x & 15;    // 0..15
    const int kc0 = kc << 7;
    const int t = threadIdx.x;          // 256

    int bs[4], ps[4];
    #pragma unroll
    for (int r = 0; r < 4; r++) {
        int m = g_sel_idx[rg * 4 + r];
        bs[r] = m >> 12; ps[r] = m & 4095;
    }

    // 512 scattered loads, 2 independent per thread
    #pragma unroll
    for (int i = 0; i < 2; i++) {
        int idx = t + (i << 8);
        int r = idx >> 7, k = idx & 127;
        f[r][k] = F[(size_t)bs[r] * CC * PP + (size_t)(kc0 + k) * PP + ps[r]];
    }
    __syncthreads();

    float a0 = 0.f, a1 = 0.f, a2 = 0.f, a3 = 0.f;
    #pragma unroll 8
    for (int k = 0; k < 128; k++) {
        float w = Wt[(size_t)(kc0 + k) * DD + t];
        a0 += f[0][k] * w;
        a1 += f[1][k] * w;
        a2 += f[2][k] * w;
        a3 += f[3][k] * w;
    }
    float* dst = g_zpart[kc] + (size_t)(rg * 4) * DD + t;
    dst[0 * DD] = a0;
    dst[1 * DD] = a1;
    dst[2 * DD] = a2;
    dst[3 * DD] = a3;
}

// =====================================================================
// Kernel 4 (launched 4th -> gets ncu capture): fused bf16x2 stats-GEMM.
//   z[m,d] = F[m,:]*W ~ A_bf16 * (Bh + Bl)  (fp32 accum, 2 MMA passes)
// 8 warps as 2m x 4n, warp tile 64x64 (better B-fragment reuse:
// ldmatrix/warp/kt 36 -> 24). Epilogue reduces sum/sumsq per column.
// =====================================================================
__global__ void __launch_bounds__(256, 1) k_mma(const float* __restrict__ F)
{
    extern __shared__ char smem[];
    const uint32_t sb = smem_u32(smem);
    const int tid = threadIdx.x;
    const int wid = tid >> 5, lane = tid & 31;
    const int wm = wid & 1, wn = wid >> 1;     // 2m x 4n
    const int m0 = blockIdx.x << 7;
    const int b = m0 >> 12, p0 = m0 & 4095;
    const float* Fb = F + (size_t)b * CC * PP + p0;

    float acc[4][8][4];
    #pragma unroll
    for (int mi = 0; mi < 4; mi++)
        #pragma unroll
        for (int n8 = 0; n8 < 8; n8++)
            #pragma unroll
            for (int q = 0; q < 4; q++) acc[mi][n8][q] = 0.f;

    // per-thread A staging: 4 float4 (row = idx>>5 of 32, col4 = idx&31)
    float4 ar[4];
    const int arow[4] = { tid >> 5, (tid >> 5) + 8, (tid >> 5) + 16, (tid >> 5) + 24 };
    const int acol4 = tid & 31;

    #define LDG_A(kb) do { \
        _Pragma("unroll") \
        for (int i = 0; i < 4; i++) \
            ar[i] = *(const float4*)(Fb + (size_t)((kb) + arow[i]) * PP + acol4 * 4); \
    } while (0)

    #define STS_A(slotbase) do { \
        _Pragma("unroll") \
        for (int i = 0; i < 4; i++) { \
            __nv_bfloat162 p0b = __floats2bfloat162_rn(ar[i].x, ar[i].y); \
            __nv_bfloat162 p1b = __floats2bfloat162_rn(ar[i].z, ar[i].w); \
            uint32_t u0 = *(uint32_t*)&p0b, u1 = *(uint32_t*)&p1b; \
            ull v = (ull)u0 | ((ull)u1 << 32); \
            uint32_t dst = (slotbase) + STG_A + swzA(arow[i], acol4 >> 1) + (acol4 & 1) * 8; \
            asm volatile("st.shared.b64 [%0], %1;" :: "r"(dst), "l"(v)); \
        } \
    } while (0)

    #define CP_B(kb, slotbase) do { \
        _Pragma("unroll") \
        for (int i = 0; i < 8; i++) { \
            int idx = tid + (i << 8); \
            int hl = idx >> 10, rem = idx & 1023; \
            int r = rem >> 2, c = rem & 3; \
            const __nv_bfloat16* src = (hl ? g_bl : g_bh) + (size_t)r * CC + (kb) + c * 8; \
            CP16((slotbase) + (hl ? STG_BL : STG_BH) + swzB(r, c), src); \
        } \
    } while (0)

    // prologue
    LDG_A(0);
    CP_B(0, sb + 0 * STGB); CP_COMMIT();
    STS_A(sb + 0 * STGB);
    LDG_A(BK);
    CP_B(BK, sb + 1 * STGB); CP_COMMIT();

    for (int kt = 0; kt < KT; kt++) {
        const uint32_t slot   = sb + (kt % 3) * STGB;
        const uint32_t slotN1 = sb + ((kt + 1) % 3) * STGB;
        const uint32_t slotN2 = sb + ((kt + 2) % 3) * STGB;

        if (kt + 1 < KT) STS_A(slotN1);          // regs hold stage kt+1
        if (kt + 2 < KT) LDG_A((kt + 2) * BK);   // prefetch stage kt+2

        if (kt < KT - 1) asm volatile("cp.async.wait_group 1;" ::: "memory");
        else             asm volatile("cp.async.wait_group 0;" ::: "memory");
        __syncthreads();
        if (kt + 2 < KT) { CP_B((kt + 2) * BK, slotN2); CP_COMMIT(); }

        const uint32_t sA = slot + STG_A;
        const uint32_t sBh = slot + STG_BH;
        const uint32_t sBl = slot + STG_BL;

        #pragma unroll
        for (int k16 = 0; k16 < 2; k16++) {
            const int kc = k16 * 2;
            const int k0 = k16 * 16;
            uint32_t ah[4][4];
            #pragma unroll
            for (int mi = 0; mi < 4; mi++) {
                int krow = k0 + (lane & 7) + ((lane >> 4) << 3);
                int mc = wm * 8 + mi * 2 + ((lane >> 3) & 1);
                LDSM4T(ah[mi][0], ah[mi][1], ah[mi][2], ah[mi][3],
                       sA + swzA(krow, mc));
            }
            #pragma unroll
            for (int g = 0; g < 4; g++) {
                int r = wn * 64 + g * 16 + (lane & 7) + ((lane >> 4) << 3);
                int cl = kc + ((lane >> 3) & 1);
                uint32_t sw = swzB(r, cl);
                uint32_t bh[4], bl[4];
                LDSM4(bh[0], bh[1], bh[2], bh[3], sBh + sw);
                LDSM4(bl[0], bl[1], bl[2], bl[3], sBl + sw);
                #pragma unroll
                for (int mi = 0; mi < 4; mi++)
                    #pragma unroll
                    for (int s2 = 0; s2 < 2; s2++)
                        MMA_BF16(acc[mi][g * 2 + s2], ah[mi], bh[2 * s2], bh[2 * s2 + 1]);
                #pragma unroll
                for (int mi = 0; mi < 4; mi++)
                    #pragma unroll
                    for (int s2 = 0; s2 < 2; s2++)
                        MMA_BF16(acc[mi][g * 2 + s2], ah[mi], bl[2 * s2], bl[2 * s2 + 1]);
            }
        }
    }

    // ---- epilogue: column sum / sumsq over this CTA's 128 rows ----
    __syncthreads();
    float* ssum = (float*)smem;         // [256]
    float* qsum = ssum + 256;           // [256]
    ssum[tid] = 0.f; qsum[tid] = 0.f;
    __syncthreads();

    #pragma unroll
    for (int n8 = 0; n8 < 8; n8++) {
        float s0 = 0.f, q0 = 0.f, s1 = 0.f, q1 = 0.f;
        #pragma unroll
        for (int mi = 0; mi < 4; mi++) {
            float a0 = acc[mi][n8][0], a1 = acc[mi][n8][1];
            float a2 = acc[mi][n8][2], a3 = acc[mi][n8][3];
            s0 += a0 + a2; q0 += a0 * a0 + a2 * a2;
            s1 += a1 + a3; q1 += a1 * a1 + a3 * a3;
        }
        #pragma unroll
        for (int off = 4; off < 32; off <<= 1) {
            s0 += __shfl_down_sync(0xffffffffu, s0, off);
            q0 += __shfl_down_sync(0xffffffffu, q0, off);
            s1 += __shfl_down_sync(0xffffffffu, s1, off);
            q1 += __shfl_down_sync(0xffffffffu, q1, off);
        }
        if (lane < 4) {
            int col = wn * 64 + n8 * 8 + lane * 2;
            atomicAdd(&ssum[col], s0);     atomicAdd(&qsum[col], q0);
            atomicAdd(&ssum[col + 1], s1); atomicAdd(&qsum[col + 1], q1);
        }
    }
    __syncthreads();
    g_psum[blockIdx.x * DD + tid] = ssum[tid];
    g_psq [blockIdx.x * DD + tid] = qsum[tid];

    #undef LDG_A
    #undef STS_A
    #undef CP_B
}

// =====================================================================
// Kernel 5: prep (grid = 3).
//   block 0: BN stats + BN/ReLU/L2-normalize the 128 selected rows
//   block 1/2: memory-bank inverse norms
// =====================================================================
__global__ void k_prep(const float* __restrict__ gamma,
                       const float* __restrict__ beta,
                       const float* __restrict__ mpos,
                       const float* __restrict__ mneg)
{
    const int blk = blockIdx.x;
    const int t = threadIdx.x;           // 256 threads
    const int warp = t >> 5, lane = t & 31;

    if (blk == 0) {
        __shared__ float s_mu[DD], s_istd[DD];
        if (t < 64) { g_pe[t] = 0.f; g_ne[t] = 0.f; }

        float s = 0.f, q = 0.f;
        #pragma unroll 4
        for (int b2 = 0; b2 < 256; b2++) {
            s += g_psum[b2 * DD + t];
            q += g_psq[b2 * DD + t];
        }
        float mu  = s * (1.0f / 32768.0f);
        float var = q * (1.0f / 32768.0f) - mu * mu;
        s_mu[t]   = mu;
        s_istd[t] = 1.0f / sqrtf(var + 1e-5f);
        __syncthreads();

        for (int sr = warp; sr < 128; sr += 8) {
            float v[8]; float ss = 0.f;
            #pragma unroll
            for (int k = 0; k < 8; k++) {
                int d = lane + 32 * k;
                float z = 0.f;
                #pragma unroll
                for (int c = 0; c < ZKC; c++) z += g_zpart[c][(size_t)sr * DD + d];
                float x = (z - s_mu[d]) * s_istd[d] * gamma[d] + beta[d];
                x = fmaxf(x, 0.f);
                v[k] = x; ss += x * x;
            }
            #pragma unroll
            for (int o = 16; o; o >>= 1) ss += __shfl_xor_sync(0xffffffffu, ss, o);
            float inv = 1.0f / (sqrtf(ss) + 1e-12f);
            #pragma unroll
            for (int k = 0; k < 8; k++) g_nf[sr * DD + lane + 32 * k] = v[k] * inv;
        }
    } else {
        const float* m = (blk == 1) ? mpos : mneg;
        const int base = (blk - 1) * NMEM;
        for (int r = warp; r < NMEM; r += 8) {
            const float* mr = m + (size_t)r * DD;
            float ss = 0.f;
            #pragma unroll
            for (int k = 0; k < 8; k++) { float x = mr[lane + 32 * k]; ss += x * x; }
            #pragma unroll
            for (int o = 16; o; o >>= 1) ss += __shfl_xor_sync(0xffffffffu, ss, o);
            if (lane == 0) g_mn[base + r] = 1.0f / (sqrtf(ss) + 1e-12f);
        }
    }
}

// =====================================================================
// Kernel 6: InfoNCE partials, 256 blocks = 64 tasks x 4 j-chunks.
// loss: 0=l1(fg local) 1=l2(bg local) 2=g1(fg global) 3=g2(bg global)
// =====================================================================
__global__ void k_nce(const float* __restrict__ mpos,
                      const float* __restrict__ mneg)
{
    const int task  = blockIdx.x >> 2;
    const int chunk = blockIdx.x & 3;
    const int loss = task >> 4;
    const int a    = task & 15;
    const int qslot = (loss & 1) ? (NS + a) : a;

    __shared__ float sq[DD];
    __shared__ float spe[8], sne[8];

    const int t = threadIdx.x;           // 256 threads
    const int warp = t >> 5, lane = t & 31;

    sq[t] = g_nf[qslot * DD + t];
    __syncthreads();

    float pe = 0.f, ne = 0.f;
    float ql[8];
    #pragma unroll
    for (int k = 0; k < 8; k++) ql[k] = sq[lane + 32 * k];

    if (loss < 2) {
        const int posbase = (loss == 0) ? 0 : NS;
        const int negbase = NS - posbase;
        const int j0 = chunk * 16;
        for (int j = j0 + warp; j < j0 + 16; j += 8) {
            const float* p = g_nf + (size_t)(posbase + j) * DD;
            float d = 0.f;
            #pragma unroll
            for (int k = 0; k < 8; k++) d += ql[k] * p[lane + 32 * k];
            #pragma unroll
            for (int o = 16; o; o >>= 1) d += __shfl_xor_sync(0xffffffffu, d, o);
            pe += expf(d * 10.0f) * g_sel_valid[posbase + j];

            const float* n2 = g_nf + (size_t)(negbase + j) * DD;
            float dn = 0.f;
            #pragma unroll
            for (int k = 0; k < 8; k++) dn += ql[k] * n2[lane + 32 * k];
            #pragma unroll
            for (int o = 16; o; o >>= 1) dn += __shfl_xor_sync(0xffffffffu, dn, o);
            ne += expf(dn * 10.0f) * g_sel_valid[negbase + j];
        }
    } else {
        const float* pb = (loss == 2) ? mpos : mneg;
        const float* nb = (loss == 2) ? mneg : mpos;
        const int pno = (loss == 2) ? 0 : NMEM;
        const int j0 = chunk * 64;
        for (int j = j0 + warp; j < j0 + 64; j += 8) {
            const float* p = pb + (size_t)j * DD;
            float d = 0.f;
            #pragma unroll
            for (int k = 0; k < 8; k++) d += ql[k] * p[lane + 32 * k];
            #pragma unroll
            for (int o = 16; o; o >>= 1) d += __shfl_xor_sync(0xffffffffu, d, o);
            pe += expf(d * g_mn[pno + j] * 10.0f);

            const float* n2 = nb + (size_t)j * DD;
            float dn = 0.f;
            #pragma unroll
            for (int k = 0; k < 8; k++) dn += ql[k] * n2[lane + 32 * k];
            #pragma unroll
            for (int o = 16; o; o >>= 1) dn += __shfl_xor_sync(0xffffffffu, dn, o);
            ne += expf(dn * g_mn[(pno ^ NMEM) + j] * 10.0f);
        }
    }

    if (lane == 0) { spe[warp] = pe; sne[warp] = ne; }
    __syncthreads();
    if (t == 0) {
        float P = 0.f, N = 0.f;
        #pragma unroll
        for (int w = 0; w < 8; w++) { P += spe[w]; N += sne[w]; }
        atomicAdd(&g_pe[task], P);
        atomicAdd(&g_ne[task], N);
    }
}

// =====================================================================
// Kernel 7: final losses + scalar output (1 block, 64 threads)
// =====================================================================
__global__ void k_out(float* __restrict__ out)
{
    __shared__ float sw2[2];
    const int t = threadIdx.x;          // 64
    const int loss = t >> 4, a = t & 15;
    const int qslot = (loss & 1) ? (NS + a) : a;

    float P = g_pe[t], N = g_ne[t];
    float lv = -logf(P / (P + N + 1e-8f) + 1e-8f) * g_sel_valid[qslot];

    #pragma unroll
    for (int o = 16; o; o >>= 1) lv += __shfl_down_sync(0xffffffffu, lv, o);
    if ((t & 31) == 0) sw2[t >> 5] = lv;
    __syncthreads();
    if (t == 0) {
        float total = sw2[0] + sw2[1];
        float n = 0.f;
        #pragma unroll
        for (int i = 0; i < 16; i++) n += g_sel_valid[i] + g_sel_valid[NS + i];
        n = fmaxf(n, 1.0f);
        out[0] = total / n;
    }
}

// =====================================================================
extern "C" void kernel_launch(void* const* d_in, const int* in_sizes, int n_in,
                              void* d_out, int out_size)
{
    const float* features = (const float*)d_in[0];
    const float* pred_ori = (const float*)d_in[1];
    const float* pred_aug = (const float*)d_in[2];
    const float* unc      = (const float*)d_in[3];
    const int*   labels   = (const int*)  d_in[4];
    const float* conv_w   = (const float*)d_in[5];
    // d_in[6] = conv_b: cancels exactly in BatchNorm -> unused
    const float* gamma    = (const float*)d_in[7];
    const float* beta     = (const float*)d_in[8];
    const float* mpos     = (const float*)d_in[9];
    const float* mneg     = (const float*)d_in[10];

    cudaFuncSetAttribute(k_mma, cudaFuncAttributeMaxDynamicSharedMemorySize, SM_MMA);

    // Order chosen so k_mma is the 4th launch (ncu -s5-c1 captures it).
    // Dependencies preserved: zsel needs select; mma needs wconv.
    k_select<<<2, 1024>>>(pred_ori, pred_aug, unc, labels);
    k_wconv<<<512, 256>>>(conv_w);
    k_zsel<<<512, 256>>>(features, conv_w);
    k_mma<<<256, 256, SM_MMA>>>(features);
    k_prep<<<3, 256>>>(gamma, beta, mpos, mneg);
    k_nce<<<256, 256>>>(mpos, mneg);
    k_out<<<1, 64>>>((float*)d_out);
}

// round 10
// speedup vs baseline: 1.4677x; 1.4677x over previous
#include <cuda_runtime.h>
#include <cuda_bf16.h>
#include <cstdint>
#include <math.h>

// Problem constants (fixed by setup_inputs)
#define NPIX 32768      // B*H*W = 8*64*64
#define PP   4096       // H*W
#define CC   2048       // channels (GEMM K)
#define DD   256        // projection dim (GEMM N)
#define NMEM 256        // memory bank rows
#define NS   64         // NUM_SAMPLES

// GEMM tiling (single-pass bf16: A_bf16 * W_bf16, stats-only consumer)
#define BK     32                  // K per stage
#define KT     (CC / BK)           // 64 k-iterations
#define STG_A  0                   // bf16 A [32 k][128 m] = 8KB
#define STG_B  8192                // bf16 B [256 n][32 k] = 16KB
#define STGB   24576
#define SM_MMA (3 * STGB)          // 73728 dynamic smem

#define ZKC    8                   // zsel k-chunks (256 channels each) — R8 measured config

typedef unsigned long long ull;

// ---------------- device scratch (static: no allocations allowed) ----------
__device__ __align__(16) __nv_bfloat16 g_bh[(size_t)DD * CC];     // W bf16, [n=d][k=c]
__device__ float g_psum[256 * DD];              // per-CTA column sums
__device__ float g_psq[256 * DD];               // per-CTA column sumsq
__device__ int   g_sel_idx[128];                // fg[0..63], bg[64..127]
__device__ float g_sel_valid[128];
__device__ float g_zpart[ZKC][128 * DD];        // per-kchunk partial z at selected rows
__device__ float g_nf[128 * DD];                // normalized selected features
__device__ float g_mn[2 * NMEM];                // memory-bank inverse norms
__device__ float g_pe[64], g_ne[64];            // per-task exp sums

// ---------------- PTX helpers (sm_100-base legal) ----------------
__device__ __forceinline__ uint32_t smem_u32(const void* p) {
    uint32_t a;
    asm("{ .reg .u64 t; cvta.to.shared.u64 t, %1; cvt.u32.u64 %0, t; }"
        : "=r"(a) : "l"(p));
    return a;
}

#define CP16(dst, src) \
    asm volatile("{ .reg .u64 p; cvta.to.global.u64 p, %1; " \
                 "cp.async.cg.shared.global [%0], [p], 16; }" \
                 :: "r"(dst), "l"(src))

#define CP_COMMIT() asm volatile("cp.async.commit_group;" ::: "memory")

#define LDSM4(r0, r1, r2, r3, addr) \
    asm volatile("ldmatrix.sync.aligned.m8n8.x4.shared.b16 {%0,%1,%2,%3}, [%4];" \
                 : "=r"(r0), "=r"(r1), "=r"(r2), "=r"(r3) : "r"(addr))

#define LDSM4T(r0, r1, r2, r3, addr) \
    asm volatile("ldmatrix.sync.aligned.m8n8.x4.trans.shared.b16 {%0,%1,%2,%3}, [%4];" \
                 : "=r"(r0), "=r"(r1), "=r"(r2), "=r"(r3) : "r"(addr))

#define MMA_BF16(c, a, b0, b1) \
    asm volatile("mma.sync.aligned.m16n8k16.row.col.f32.bf16.bf16.f32 " \
                 "{%0,%1,%2,%3}, {%4,%5,%6,%7}, {%8,%9}, {%0,%1,%2,%3};" \
                 : "+f"((c)[0]), "+f"((c)[1]), "+f"((c)[2]), "+f"((c)[3]) \
                 : "r"((a)[0]), "r"((a)[1]), "r"((a)[2]), "r"((a)[3]), \
                   "r"(b0), "r"(b1))

// B-tile swizzle (rows of 64B, 16B chunks c 0..3) — proven in R4
__device__ __forceinline__ uint32_t swzB(int r, int c) {
    return (uint32_t)(r * 64 + 16 * (c ^ ((r >> 1) & 3)));
}
// A-tile swizzle: [k rows][128 m bf16 = 256B = 16 chunks]
__device__ __forceinline__ uint32_t swzA(int k, int mc) {
    return (uint32_t)(k * 256 + 16 * (mc ^ (k & 15)));
}

// =====================================================================
// Kernel 1: hard-sample mining. block 0 -> fg (label==1), block 1 -> bg.
// Iterative block-argmax (64 rounds) replicating jax.lax.top_k exactly.
// =====================================================================
__global__ void k_select(const float* __restrict__ pred_ori,
                         const float* __restrict__ pred_aug,
                         const float* __restrict__ unc,
                         const int*   __restrict__ labels)
{
    const int cls = blockIdx.x;          // 0: fg, 1: bg
    const int tid = threadIdx.x;         // 1024 threads
    const int want = cls ? 0 : 1;

    float sc[32];
    #pragma unroll
    for (int i = 0; i < 32; i++) {
        int n = tid + (i << 10);
        int b = n >> 12, p = n & 4095;
        const float* po = pred_ori + (size_t)b * 2 * PP + p;
        const float* pa = pred_aug + (size_t)b * 2 * PP + p;
        int io = po[PP] > po[0];
        int ia = pa[PP] > pa[0];
        float u = unc[n];
        bool ok = (io == ia) && (u > 0.5f) && (labels[n] == want);
        sc[i] = ok ? u : -1e9f;
    }

    float bv = -INFINITY; int bi = -1;
    #pragma unroll
    for (int i = 0; i < 32; i++) {
        int n = tid + (i << 10);
        if (sc[i] > bv || (sc[i] == bv && n < bi)) { bv = sc[i]; bi = n; }
    }

    __shared__ float wv[32];
    __shared__ int   wi[32];
    __shared__ int   winner;

    for (int it = 0; it < NS; it++) {
        float v = bv; int ix = bi;
        #pragma unroll
        for (int o = 16; o; o >>= 1) {
            float ov = __shfl_down_sync(0xffffffffu, v, o);
            int   oi = __shfl_down_sync(0xffffffffu, ix, o);
            if (ov > v || (ov == v && oi < ix)) { v = ov; ix = oi; }
        }
        if ((tid & 31) == 0) { wv[tid >> 5] = v; wi[tid >> 5] = ix; }
        __syncthreads();
        if (tid < 32) {
            v = wv[tid]; ix = wi[tid];
            #pragma unroll
            for (int o = 16; o; o >>= 1) {
                float ov = __shfl_down_sync(0xffffffffu, v, o);
                int   oi = __shfl_down_sync(0xffffffffu, ix, o);
                if (ov > v || (ov == v && oi < ix)) { v = ov; ix = oi; }
            }
            if (tid == 0) {
                winner = ix;
                g_sel_idx[cls * NS + it]   = ix;
                g_sel_valid[cls * NS + it] = (v > -5e8f) ? 1.0f : 0.0f;
            }
        }
        __syncthreads();
        int wn = winner;
        if ((wn & 1023) == tid) {
            sc[wn >> 10] = -INFINITY;
            bv = -INFINITY; bi = -1;
            #pragma unroll
            for (int i = 0; i < 32; i++) {
                int n = tid + (i << 10);
                if (sc[i] > bv || (sc[i] == bv && n < bi)) { bv = sc[i]; bi = n; }
            }
        }
        __syncthreads();
    }
}

// =====================================================================
// Kernel 2: W -> bf16, transposed to [n=d][k=c] (K-major).
// Stats-only consumer: single bf16 rounding is sufficient (var bias
// ~1e-4 rel; selected rows use exact fp32 via k_zsel).
// conv_b omitted: cancels exactly in BatchNorm.
// =====================================================================
__global__ void __launch_bounds__(256) k_wconv(const float* __restrict__ Wt)
{
    __shared__ float s[32][33];
    const int bid = blockIdx.x;         // 512 blocks
    const int tid = threadIdx.x;
    const int li = tid >> 5;            // 0..7
    const int lj = tid & 31;
    const int d0 = (bid & 7) << 5, c0 = (bid >> 3) << 5;

    #pragma unroll
    for (int i4 = 0; i4 < 4; i4++) {
        int i = li + i4 * 8;
        s[i][lj] = Wt[(size_t)(c0 + i) * DD + d0 + lj];
    }
    __syncthreads();
    #pragma unroll
    for (int i4 = 0; i4 < 4; i4++) {
        int r = li + i4 * 8;            // d-local
        g_bh[(size_t)(d0 + r) * CC + c0 + lj] = __float2bfloat16(s[lj][r]);
    }
}

// =====================================================================
// Kernel 3 (launched 3rd): exact fp32 z partials for the 128 selected
// rows. 256 blocks = 32 row-groups (4 rows) x 8 k-chunks (256 ch) —
// the R8-measured configuration (37.9us).
// =====================================================================
__global__ void __launch_bounds__(256) k_zsel(const float* __restrict__ F,
                                              const float* __restrict__ Wt)
{
    __shared__ float f[4][256];
    const int rg  = blockIdx.x >> 3;    // 0..31
    const int kc  = blockIdx.x & 7;     // 0..7
    const int kc0 = kc << 8;
    const int t = threadIdx.x;          // 256

    int bs[4], ps[4];
    #pragma unroll
    for (int r = 0; r < 4; r++) {
        int m = g_sel_idx[rg * 4 + r];
        bs[r] = m >> 12; ps[r] = m & 4095;
    }

    // 1024 scattered loads, 4 independent per thread
    #pragma unroll
    for (int i = 0; i < 4; i++) {
        int idx = t + (i << 8);
        int r = idx >> 8, k = idx & 255;
        f[r][k] = F[(size_t)bs[r] * CC * PP + (size_t)(kc0 + k) * PP + ps[r]];
    }
    __syncthreads();

    float a0 = 0.f, a1 = 0.f, a2 = 0.f, a3 = 0.f;
    #pragma unroll 8
    for (int k = 0; k < 256; k++) {
        float w = Wt[(size_t)(kc0 + k) * DD + t];
        a0 += f[0][k] * w;
        a1 += f[1][k] * w;
        a2 += f[2][k] * w;
        a3 += f[3][k] * w;
    }
    float* dst = g_zpart[kc] + (size_t)(rg * 4) * DD + t;
    dst[0 * DD] = a0;
    dst[1 * DD] = a1;
    dst[2 * DD] = a2;
    dst[3 * DD] = a3;
}

// =====================================================================
// Kernel 4 (launched 4th -> gets ncu capture): fused bf16 stats-GEMM.
//   z[m,d] ~ A_bf16 * W_bf16  (fp32 accum, SINGLE pass)
// 8 warps as 2m x 4n, warp tile 64x64. SMEM ldsm traffic per kt:
// 64KB (was 96KB with the Bl pass); MMA count halved.
// Epilogue reduces sum/sumsq per column; z never stored.
// =====================================================================
__global__ void __launch_bounds__(256, 1) k_mma(const float* __restrict__ F)
{
    extern __shared__ char smem[];
    const uint32_t sb = smem_u32(smem);
    const int tid = threadIdx.x;
    const int wid = tid >> 5, lane = tid & 31;
    const int wm = wid & 1, wn = wid >> 1;     // 2m x 4n
    const int m0 = blockIdx.x << 7;
    const int b = m0 >> 12, p0 = m0 & 4095;
    const float* Fb = F + (size_t)b * CC * PP + p0;

    float acc[4][8][4];
    #pragma unroll
    for (int mi = 0; mi < 4; mi++)
        #pragma unroll
        for (int n8 = 0; n8 < 8; n8++)
            #pragma unroll
            for (int q = 0; q < 4; q++) acc[mi][n8][q] = 0.f;

    // per-thread A staging: 4 float4 (row = idx>>5 of 32, col4 = idx&31)
    float4 ar[4];
    const int arow[4] = { tid >> 5, (tid >> 5) + 8, (tid >> 5) + 16, (tid >> 5) + 24 };
    const int acol4 = tid & 31;

    #define LDG_A(kb) do { \
        _Pragma("unroll") \
        for (int i = 0; i < 4; i++) \
            ar[i] = *(const float4*)(Fb + (size_t)((kb) + arow[i]) * PP + acol4 * 4); \
    } while (0)

    #define STS_A(slotbase) do { \
        _Pragma("unroll") \
        for (int i = 0; i < 4; i++) { \
            __nv_bfloat162 p0b = __floats2bfloat162_rn(ar[i].x, ar[i].y); \
            __nv_bfloat162 p1b = __floats2bfloat162_rn(ar[i].z, ar[i].w); \
            uint32_t u0 = *(uint32_t*)&p0b, u1 = *(uint32_t*)&p1b; \
            ull v = (ull)u0 | ((ull)u1 << 32); \
            uint32_t dst = (slotbase) + STG_A + swzA(arow[i], acol4 >> 1) + (acol4 & 1) * 8; \
            asm volatile("st.shared.b64 [%0], %1;" :: "r"(dst), "l"(v)); \
        } \
    } while (0)

    #define CP_B(kb, slotbase) do { \
        _Pragma("unroll") \
        for (int i = 0; i < 4; i++) { \
            int idx = tid + (i << 8); \
            int r = idx >> 2, c = idx & 3; \
            const __nv_bfloat16* src = g_bh + (size_t)r * CC + (kb) + c * 8; \
            CP16((slotbase) + STG_B + swzB(r, c), src); \
        } \
    } while (0)

    // prologue
    LDG_A(0);
    CP_B(0, sb + 0 * STGB); CP_COMMIT();
    STS_A(sb + 0 * STGB);
    LDG_A(BK);
    CP_B(BK, sb + 1 * STGB); CP_COMMIT();

    for (int kt = 0; kt < KT; kt++) {
        const uint32_t slot   = sb + (kt % 3) * STGB;
        const uint32_t slotN1 = sb + ((kt + 1) % 3) * STGB;
        const uint32_t slotN2 = sb + ((kt + 2) % 3) * STGB;

        if (kt + 1 < KT) STS_A(slotN1);          // regs hold stage kt+1
        if (kt + 2 < KT) LDG_A((kt + 2) * BK);   // prefetch stage kt+2

        if (kt < KT - 1) asm volatile("cp.async.wait_group 1;" ::: "memory");
        else             asm volatile("cp.async.wait_group 0;" ::: "memory");
        __syncthreads();
        if (kt + 2 < KT) { CP_B((kt + 2) * BK, slotN2); CP_COMMIT(); }

        const uint32_t sA = slot + STG_A;
        const uint32_t sB = slot + STG_B;

        #pragma unroll
        for (int k16 = 0; k16 < 2; k16++) {
            const int kc = k16 * 2;
            const int k0 = k16 * 16;
            uint32_t ah[4][4];
            #pragma unroll
            for (int mi = 0; mi < 4; mi++) {
                int krow = k0 + (lane & 7) + ((lane >> 4) << 3);
                int mc = wm * 8 + mi * 2 + ((lane >> 3) & 1);
                LDSM4T(ah[mi][0], ah[mi][1], ah[mi][2], ah[mi][3],
                       sA + swzA(krow, mc));
            }
            #pragma unroll
            for (int g = 0; g < 4; g++) {
                int r = wn * 64 + g * 16 + (lane & 7) + ((lane >> 4) << 3);
                int cl = kc + ((lane >> 3) & 1);
                uint32_t bh[4];
                LDSM4(bh[0], bh[1], bh[2], bh[3], sB + swzB(r, cl));
                #pragma unroll
                for (int mi = 0; mi < 4; mi++)
                    #pragma unroll
                    for (int s2 = 0; s2 < 2; s2++)
                        MMA_BF16(acc[mi][g * 2 + s2], ah[mi], bh[2 * s2], bh[2 * s2 + 1]);
            }
        }
    }

    // ---- epilogue: column sum / sumsq over this CTA's 128 rows ----
    __syncthreads();
    float* ssum = (float*)smem;         // [256]
    float* qsum = ssum + 256;           // [256]
    ssum[tid] = 0.f; qsum[tid] = 0.f;
    __syncthreads();

    #pragma unroll
    for (int n8 = 0; n8 < 8; n8++) {
        float s0 = 0.f, q0 = 0.f, s1 = 0.f, q1 = 0.f;
        #pragma unroll
        for (int mi = 0; mi < 4; mi++) {
            float a0 = acc[mi][n8][0], a1 = acc[mi][n8][1];
            float a2 = acc[mi][n8][2], a3 = acc[mi][n8][3];
            s0 += a0 + a2; q0 += a0 * a0 + a2 * a2;
            s1 += a1 + a3; q1 += a1 * a1 + a3 * a3;
        }
        #pragma unroll
        for (int off = 4; off < 32; off <<= 1) {
            s0 += __shfl_down_sync(0xffffffffu, s0, off);
            q0 += __shfl_down_sync(0xffffffffu, q0, off);
            s1 += __shfl_down_sync(0xffffffffu, s1, off);
            q1 += __shfl_down_sync(0xffffffffu, q1, off);
        }
        if (lane < 4) {
            int col = wn * 64 + n8 * 8 + lane * 2;
            atomicAdd(&ssum[col], s0);     atomicAdd(&qsum[col], q0);
            atomicAdd(&ssum[col + 1], s1); atomicAdd(&qsum[col + 1], q1);
        }
    }
    __syncthreads();
    g_psum[blockIdx.x * DD + tid] = ssum[tid];
    g_psq [blockIdx.x * DD + tid] = qsum[tid];

    #undef LDG_A
    #undef STS_A
    #undef CP_B
}

// =====================================================================
// Kernel 5: prep (grid = 3).
//   block 0: BN stats + BN/ReLU/L2-normalize the 128 selected rows
//   block 1/2: memory-bank inverse norms
// =====================================================================
__global__ void k_prep(const float* __restrict__ gamma,
                       const float* __restrict__ beta,
                       const float* __restrict__ mpos,
                       const float* __restrict__ mneg)
{
    const int blk = blockIdx.x;
    const int t = threadIdx.x;           // 256 threads
    const int warp = t >> 5, lane = t & 31;

    if (blk == 0) {
        __shared__ float s_mu[DD], s_istd[DD];
        if (t < 64) { g_pe[t] = 0.f; g_ne[t] = 0.f; }

        float s = 0.f, q = 0.f;
        #pragma unroll 4
        for (int b2 = 0; b2 < 256; b2++) {
            s += g_psum[b2 * DD + t];
            q += g_psq[b2 * DD + t];
        }
        float mu  = s * (1.0f / 32768.0f);
        float var = q * (1.0f / 32768.0f) - mu * mu;
        s_mu[t]   = mu;
        s_istd[t] = 1.0f / sqrtf(var + 1e-5f);
        __syncthreads();

        for (int sr = warp; sr < 128; sr += 8) {
            float v[8]; float ss = 0.f;
            #pragma unroll
            for (int k = 0; k < 8; k++) {
                int d = lane + 32 * k;
                float z = 0.f;
                #pragma unroll
                for (int c = 0; c < ZKC; c++) z += g_zpart[c][(size_t)sr * DD + d];
                float x = (z - s_mu[d]) * s_istd[d] * gamma[d] + beta[d];
                x = fmaxf(x, 0.f);
                v[k] = x; ss += x * x;
            }
            #pragma unroll
            for (int o = 16; o; o >>= 1) ss += __shfl_xor_sync(0xffffffffu, ss, o);
            float inv = 1.0f / (sqrtf(ss) + 1e-12f);
            #pragma unroll
            for (int k = 0; k < 8; k++) g_nf[sr * DD + lane + 32 * k] = v[k] * inv;
        }
    } else {
        const float* m = (blk == 1) ? mpos : mneg;
        const int base = (blk - 1) * NMEM;
        for (int r = warp; r < NMEM; r += 8) {
            const float* mr = m + (size_t)r * DD;
            float ss = 0.f;
            #pragma unroll
            for (int k = 0; k < 8; k++) { float x = mr[lane + 32 * k]; ss += x * x; }
            #pragma unroll
            for (int o = 16; o; o >>= 1) ss += __shfl_xor_sync(0xffffffffu, ss, o);
            if (lane == 0) g_mn[base + r] = 1.0f / (sqrtf(ss) + 1e-12f);
        }
    }
}

// =====================================================================
// Kernel 6: InfoNCE partials, 256 blocks = 64 tasks x 4 j-chunks.
// loss: 0=l1(fg local) 1=l2(bg local) 2=g1(fg global) 3=g2(bg global)
// =====================================================================
__global__ void k_nce(const float* __restrict__ mpos,
                      const float* __restrict__ mneg)
{
    const int task  = blockIdx.x >> 2;
    const int chunk = blockIdx.x & 3;
    const int loss = task >> 4;
    const int a    = task & 15;
    const int qslot = (loss & 1) ? (NS + a) : a;

    __shared__ float sq[DD];
    __shared__ float spe[8], sne[8];

    const int t = threadIdx.x;           // 256 threads
    const int warp = t >> 5, lane = t & 31;

    sq[t] = g_nf[qslot * DD + t];
    __syncthreads();

    float pe = 0.f, ne = 0.f;
    float ql[8];
    #pragma unroll
    for (int k = 0; k < 8; k++) ql[k] = sq[lane + 32 * k];

    if (loss < 2) {
        const int posbase = (loss == 0) ? 0 : NS;
        const int negbase = NS - posbase;
        const int j0 = chunk * 16;
        for (int j = j0 + warp; j < j0 + 16; j += 8) {
            const float* p = g_nf + (size_t)(posbase + j) * DD;
            float d = 0.f;
            #pragma unroll
            for (int k = 0; k < 8; k++) d += ql[k] * p[lane + 32 * k];
            #pragma unroll
            for (int o = 16; o; o >>= 1) d += __shfl_xor_sync(0xffffffffu, d, o);
            pe += expf(d * 10.0f) * g_sel_valid[posbase + j];

            const float* n2 = g_nf + (size_t)(negbase + j) * DD;
            float dn = 0.f;
            #pragma unroll
            for (int k = 0; k < 8; k++) dn += ql[k] * n2[lane + 32 * k];
            #pragma unroll
            for (int o = 16; o; o >>= 1) dn += __shfl_xor_sync(0xffffffffu, dn, o);
            ne += expf(dn * 10.0f) * g_sel_valid[negbase + j];
        }
    } else {
        const float* pb = (loss == 2) ? mpos : mneg;
        const float* nb = (loss == 2) ? mneg : mpos;
        const int pno = (loss == 2) ? 0 : NMEM;
        const int j0 = chunk * 64;
        for (int j = j0 + warp; j < j0 + 64; j += 8) {
            const float* p = pb + (size_t)j * DD;
            float d = 0.f;
            #pragma unroll
            for (int k = 0; k < 8; k++) d += ql[k] * p[lane + 32 * k];
            #pragma unroll
            for (int o = 16; o; o >>= 1) d += __shfl_xor_sync(0xffffffffu, d, o);
            pe += expf(d * g_mn[pno + j] * 10.0f);

            const float* n2 = nb + (size_t)j * DD;
            float dn = 0.f;
            #pragma unroll
            for (int k = 0; k < 8; k++) dn += ql[k] * n2[lane + 32 * k];
            #pragma unroll
            for (int o = 16; o; o >>= 1) dn += __shfl_xor_sync(0xffffffffu, dn, o);
            ne += expf(dn * g_mn[(pno ^ NMEM) + j] * 10.0f);
        }
    }

    if (lane == 0) { spe[warp] = pe; sne[warp] = ne; }
    __syncthreads();
    if (t == 0) {
        float P = 0.f, N = 0.f;
        #pragma unroll
        for (int w = 0; w < 8; w++) { P += spe[w]; N += sne[w]; }
        atomicAdd(&g_pe[task], P);
        atomicAdd(&g_ne[task], N);
    }
}

// =====================================================================
// Kernel 7: final losses + scalar output (1 block, 64 threads)
// =====================================================================
__global__ void k_out(float* __restrict__ out)
{
    __shared__ float sw2[2];
    const int t = threadIdx.x;          // 64
    const int loss = t >> 4, a = t & 15;
    const int qslot = (loss & 1) ? (NS + a) : a;

    float P = g_pe[t], N = g_ne[t];
    float lv = -logf(P / (P + N + 1e-8f) + 1e-8f) * g_sel_valid[qslot];

    #pragma unroll
    for (int o = 16; o; o >>= 1) lv += __shfl_down_sync(0xffffffffu, lv, o);
    if ((t & 31) == 0) sw2[t >> 5] = lv;
    __syncthreads();
    if (t == 0) {
        float total = sw2[0] + sw2[1];
        float n = 0.f;
        #pragma unroll
        for (int i = 0; i < 16; i++) n += g_sel_valid[i] + g_sel_valid[NS + i];
        n = fmaxf(n, 1.0f);
        out[0] = total / n;
    }
}

// =====================================================================
extern "C" void kernel_launch(void* const* d_in, const int* in_sizes, int n_in,
                              void* d_out, int out_size)
{
    const float* features = (const float*)d_in[0];
    const float* pred_ori = (const float*)d_in[1];
    const float* pred_aug = (const float*)d_in[2];
    const float* unc      = (const float*)d_in[3];
    const int*   labels   = (const int*)  d_in[4];
    const float* conv_w   = (const float*)d_in[5];
    // d_in[6] = conv_b: cancels exactly in BatchNorm -> unused
    const float* gamma    = (const float*)d_in[7];
    const float* beta     = (const float*)d_in[8];
    const float* mpos     = (const float*)d_in[9];
    const float* mneg     = (const float*)d_in[10];

    cudaFuncSetAttribute(k_mma, cudaFuncAttributeMaxDynamicSharedMemorySize, SM_MMA);

    // k_mma is the 4th launch (ncu -s5-c1 captures it).
    k_select<<<2, 1024>>>(pred_ori, pred_aug, unc, labels);
    k_wconv<<<512, 256>>>(conv_w);
    k_zsel<<<256, 256>>>(features, conv_w);
    k_mma<<<256, 256, SM_MMA>>>(features);
    k_prep<<<3, 256>>>(gamma, beta, mpos, mneg);
    k_nce<<<256, 256>>>(mpos, mneg);
    k_out<<<1, 64>>>((float*)d_out);
}

// round 13
// speedup vs baseline: 2.0819x; 1.4185x over previous
#include <cuda_runtime.h>
#include <cuda_bf16.h>
#include <cstdint>
#include <math.h>

// Problem constants (fixed by setup_inputs)
#define NPIX 32768      // B*H*W = 8*64*64
#define PP   4096       // H*W
#define CC   2048       // channels (GEMM K)
#define DD   256        // projection dim (GEMM N)
#define NMEM 256        // memory bank rows
#define NS   64         // NUM_SAMPLES

// GEMM tiling (single-pass bf16: A_bf16 * W_bf16, stats-only consumer)
#define BK     32                  // K per stage
#define KT     (CC / BK)           // 64 k-iterations
#define STG_A  0                   // bf16 A [32 k][128 m] = 8KB
#define STG_B  8192                // bf16 B [256 n][32 k] = 16KB
#define STGB   24576
#define SM_MMA (3 * STGB)          // 73728 dynamic smem

#define ZKC    8                   // zsel k-chunks (256 channels each) — R8 measured config

typedef unsigned long long ull;

// ---------------- device scratch (static: no allocations allowed) ----------
__device__ __align__(16) __nv_bfloat16 g_bh[(size_t)DD * CC];     // W bf16, [n=d][k=c]
__device__ float g_psum[256 * DD];              // per-CTA column sums
__device__ float g_psq[256 * DD];               // per-CTA column sumsq
__device__ float g_mu[DD], g_istd[DD];          // BN stats
__device__ int   g_sel_idx[128];                // fg[0..63], bg[64..127]
__device__ float g_sel_valid[128];
__device__ float g_zpart[ZKC][128 * DD];        // per-kchunk partial z at selected rows
__device__ float g_nf[128 * DD];                // normalized selected features
__device__ float g_mn[2 * NMEM];                // memory-bank inverse norms
__device__ float g_pe[64], g_ne[64];            // per-task exp sums

// ---------------- PTX helpers (sm_100-base legal) ----------------
__device__ __forceinline__ uint32_t smem_u32(const void* p) {
    uint32_t a;
    asm("{ .reg .u64 t; cvta.to.shared.u64 t, %1; cvt.u32.u64 %0, t; }"
        : "=r"(a) : "l"(p));
    return a;
}

#define CP16(dst, src) \
    asm volatile("{ .reg .u64 p; cvta.to.global.u64 p, %1; " \
                 "cp.async.cg.shared.global [%0], [p], 16; }" \
                 :: "r"(dst), "l"(src))

#define CP_COMMIT() asm volatile("cp.async.commit_group;" ::: "memory")

#define LDSM4(r0, r1, r2, r3, addr) \
    asm volatile("ldmatrix.sync.aligned.m8n8.x4.shared.b16 {%0,%1,%2,%3}, [%4];" \
                 : "=r"(r0), "=r"(r1), "=r"(r2), "=r"(r3) : "r"(addr))

#define LDSM4T(r0, r1, r2, r3, addr) \
    asm volatile("ldmatrix.sync.aligned.m8n8.x4.trans.shared.b16 {%0,%1,%2,%3}, [%4];" \
                 : "=r"(r0), "=r"(r1), "=r"(r2), "=r"(r3) : "r"(addr))

#define MMA_BF16(c, a, b0, b1) \
    asm volatile("mma.sync.aligned.m16n8k16.row.col.f32.bf16.bf16.f32 " \
                 "{%0,%1,%2,%3}, {%4,%5,%6,%7}, {%8,%9}, {%0,%1,%2,%3};" \
                 : "+f"((c)[0]), "+f"((c)[1]), "+f"((c)[2]), "+f"((c)[3]) \
                 : "r"((a)[0]), "r"((a)[1]), "r"((a)[2]), "r"((a)[3]), \
                   "r"(b0), "r"(b1))

// B-tile swizzle (rows of 64B, 16B chunks c 0..3) — proven in R4
__device__ __forceinline__ uint32_t swzB(int r, int c) {
    return (uint32_t)(r * 64 + 16 * (c ^ ((r >> 1) & 3)));
}
// A-tile swizzle: [k rows][128 m bf16 = 256B = 16 chunks]
__device__ __forceinline__ uint32_t swzA(int k, int mc) {
    return (uint32_t)(k * 256 + 16 * (mc ^ (k & 15)));
}

// =====================================================================
// Kernel: hard-sample mining. block 0 -> fg (label==1), block 1 -> bg.
// Iterative block-argmax (64 rounds) replicating jax.lax.top_k exactly.
// =====================================================================
__global__ void k_select(const float* __restrict__ pred_ori,
                         const float* __restrict__ pred_aug,
                         const float* __restrict__ unc,
                         const int*   __restrict__ labels)
{
    const int cls = blockIdx.x;          // 0: fg, 1: bg
    const int tid = threadIdx.x;         // 1024 threads
    const int want = cls ? 0 : 1;

    float sc[32];
    #pragma unroll
    for (int i = 0; i < 32; i++) {
        int n = tid + (i << 10);
        int b = n >> 12, p = n & 4095;
        const float* po = pred_ori + (size_t)b * 2 * PP + p;
        const float* pa = pred_aug + (size_t)b * 2 * PP + p;
        int io = po[PP] > po[0];
        int ia = pa[PP] > pa[0];
        float u = unc[n];
        bool ok = (io == ia) && (u > 0.5f) && (labels[n] == want);
        sc[i] = ok ? u : -1e9f;
    }

    float bv = -INFINITY; int bi = -1;
    #pragma unroll
    for (int i = 0; i < 32; i++) {
        int n = tid + (i << 10);
        if (sc[i] > bv || (sc[i] == bv && n < bi)) { bv = sc[i]; bi = n; }
    }

    __shared__ float wv[32];
    __shared__ int   wi[32];
    __shared__ int   winner;

    for (int it = 0; it < NS; it++) {
        float v = bv; int ix = bi;
        #pragma unroll
        for (int o = 16; o; o >>= 1) {
            float ov = __shfl_down_sync(0xffffffffu, v, o);
            int   oi = __shfl_down_sync(0xffffffffu, ix, o);
            if (ov > v || (ov == v && oi < ix)) { v = ov; ix = oi; }
        }
        if ((tid & 31) == 0) { wv[tid >> 5] = v; wi[tid >> 5] = ix; }
        __syncthreads();
        if (tid < 32) {
            v = wv[tid]; ix = wi[tid];
            #pragma unroll
            for (int o = 16; o; o >>= 1) {
                float ov = __shfl_down_sync(0xffffffffu, v, o);
                int   oi = __shfl_down_sync(0xffffffffu, ix, o);
                if (ov > v || (ov == v && oi < ix)) { v = ov; ix = oi; }
            }
            if (tid == 0) {
                winner = ix;
                g_sel_idx[cls * NS + it]   = ix;
                g_sel_valid[cls * NS + it] = (v > -5e8f) ? 1.0f : 0.0f;
            }
        }
        __syncthreads();
        int wn = winner;
        if ((wn & 1023) == tid) {
            sc[wn >> 10] = -INFINITY;
            bv = -INFINITY; bi = -1;
            #pragma unroll
            for (int i = 0; i < 32; i++) {
                int n = tid + (i << 10);
                if (sc[i] > bv || (sc[i] == bv && n < bi)) { bv = sc[i]; bi = n; }
            }
        }
        __syncthreads();
    }
}

// =====================================================================
// Kernel: W -> bf16, transposed to [n=d][k=c] (K-major).
// conv_b omitted: cancels exactly in BatchNorm.
// =====================================================================
__global__ void __launch_bounds__(256) k_wconv(const float* __restrict__ Wt)
{
    __shared__ float s[32][33];
    const int bid = blockIdx.x;         // 512 blocks
    const int tid = threadIdx.x;
    const int li = tid >> 5;            // 0..7
    const int lj = tid & 31;
    const int d0 = (bid & 7) << 5, c0 = (bid >> 3) << 5;

    #pragma unroll
    for (int i4 = 0; i4 < 4; i4++) {
        int i = li + i4 * 8;
        s[i][lj] = Wt[(size_t)(c0 + i) * DD + d0 + lj];
    }
    __syncthreads();
    #pragma unroll
    for (int i4 = 0; i4 < 4; i4++) {
        int r = li + i4 * 8;            // d-local
        g_bh[(size_t)(d0 + r) * CC + c0 + lj] = __float2bfloat16(s[lj][r]);
    }
}

// =====================================================================
// Kernel: exact fp32 z partials for the 128 selected rows.
// 256 blocks = 32 row-groups (4 rows) x 8 k-chunks — R8 measured config.
// =====================================================================
__global__ void __launch_bounds__(256) k_zsel(const float* __restrict__ F,
                                              const float* __restrict__ Wt)
{
    __shared__ float f[4][256];
    const int rg  = blockIdx.x >> 3;    // 0..31
    const int kc  = blockIdx.x & 7;     // 0..7
    const int kc0 = kc << 8;
    const int t = threadIdx.x;          // 256

    int bs[4], ps[4];
    #pragma unroll
    for (int r = 0; r < 4; r++) {
        int m = g_sel_idx[rg * 4 + r];
        bs[r] = m >> 12; ps[r] = m & 4095;
    }

    #pragma unroll
    for (int i = 0; i < 4; i++) {
        int idx = t + (i << 8);
        int r = idx >> 8, k = idx & 255;
        f[r][k] = F[(size_t)bs[r] * CC * PP + (size_t)(kc0 + k) * PP + ps[r]];
    }
    __syncthreads();

    float a0 = 0.f, a1 = 0.f, a2 = 0.f, a3 = 0.f;
    #pragma unroll 8
    for (int k = 0; k < 256; k++) {
        float w = Wt[(size_t)(kc0 + k) * DD + t];
        a0 += f[0][k] * w;
        a1 += f[1][k] * w;
        a2 += f[2][k] * w;
        a3 += f[3][k] * w;
    }
    float* dst = g_zpart[kc] + (size_t)(rg * 4) * DD + t;
    dst[0 * DD] = a0;
    dst[1 * DD] = a1;
    dst[2 * DD] = a2;
    dst[3 * DD] = a3;
}

// =====================================================================
// Kernel (4th issued -> ncu capture): fused bf16 stats-GEMM.
// Measured R10: 130.7us = mma.sync ceiling. UNCHANGED.
// =====================================================================
__global__ void __launch_bounds__(256, 1) k_mma(const float* __restrict__ F)
{
    extern __shared__ char smem[];
    const uint32_t sb = smem_u32(smem);
    const int tid = threadIdx.x;
    const int wid = tid >> 5, lane = tid & 31;
    const int wm = wid & 1, wn = wid >> 1;     // 2m x 4n
    const int m0 = blockIdx.x << 7;
    const int b = m0 >> 12, p0 = m0 & 4095;
    const float* Fb = F + (size_t)b * CC * PP + p0;

    float acc[4][8][4];
    #pragma unroll
    for (int mi = 0; mi < 4; mi++)
        #pragma unroll
        for (int n8 = 0; n8 < 8; n8++)
            #pragma unroll
            for (int q = 0; q < 4; q++) acc[mi][n8][q] = 0.f;

    float4 ar[4];
    const int arow[4] = { tid >> 5, (tid >> 5) + 8, (tid >> 5) + 16, (tid >> 5) + 24 };
    const int acol4 = tid & 31;

    #define LDG_A(kb) do { \
        _Pragma("unroll") \
        for (int i = 0; i < 4; i++) \
            ar[i] = *(const float4*)(Fb + (size_t)((kb) + arow[i]) * PP + acol4 * 4); \
    } while (0)

    #define STS_A(slotbase) do { \
        _Pragma("unroll") \
        for (int i = 0; i < 4; i++) { \
            __nv_bfloat162 p0b = __floats2bfloat162_rn(ar[i].x, ar[i].y); \
            __nv_bfloat162 p1b = __floats2bfloat162_rn(ar[i].z, ar[i].w); \
            uint32_t u0 = *(uint32_t*)&p0b, u1 = *(uint32_t*)&p1b; \
            ull v = (ull)u0 | ((ull)u1 << 32); \
            uint32_t dst = (slotbase) + STG_A + swzA(arow[i], acol4 >> 1) + (acol4 & 1) * 8; \
            asm volatile("st.shared.b64 [%0], %1;" :: "r"(dst), "l"(v)); \
        } \
    } while (0)

    #define CP_B(kb, slotbase) do { \
        _Pragma("unroll") \
        for (int i = 0; i < 4; i++) { \
            int idx = tid + (i << 8); \
            int r = idx >> 2, c = idx & 3; \
            const __nv_bfloat16* src = g_bh + (size_t)r * CC + (kb) + c * 8; \
            CP16((slotbase) + STG_B + swzB(r, c), src); \
        } \
    } while (0)

    // prologue
    LDG_A(0);
    CP_B(0, sb + 0 * STGB); CP_COMMIT();
    STS_A(sb + 0 * STGB);
    LDG_A(BK);
    CP_B(BK, sb + 1 * STGB); CP_COMMIT();

    for (int kt = 0; kt < KT; kt++) {
        const uint32_t slot   = sb + (kt % 3) * STGB;
        const uint32_t slotN1 = sb + ((kt + 1) % 3) * STGB;
        const uint32_t slotN2 = sb + ((kt + 2) % 3) * STGB;

        if (kt + 1 < KT) STS_A(slotN1);
        if (kt + 2 < KT) LDG_A((kt + 2) * BK);

        if (kt < KT - 1) asm volatile("cp.async.wait_group 1;" ::: "memory");
        else             asm volatile("cp.async.wait_group 0;" ::: "memory");
        __syncthreads();
        if (kt + 2 < KT) { CP_B((kt + 2) * BK, slotN2); CP_COMMIT(); }

        const uint32_t sA = slot + STG_A;
        const uint32_t sB = slot + STG_B;

        #pragma unroll
        for (int k16 = 0; k16 < 2; k16++) {
            const int kc = k16 * 2;
            const int k0 = k16 * 16;
            uint32_t ah[4][4];
            #pragma unroll
            for (int mi = 0; mi < 4; mi++) {
                int krow = k0 + (lane & 7) + ((lane >> 4) << 3);
                int mc = wm * 8 + mi * 2 + ((lane >> 3) & 1);
                LDSM4T(ah[mi][0], ah[mi][1], ah[mi][2], ah[mi][3],
                       sA + swzA(krow, mc));
            }
            #pragma unroll
            for (int g = 0; g < 4; g++) {
                int r = wn * 64 + g * 16 + (lane & 7) + ((lane >> 4) << 3);
                int cl = kc + ((lane >> 3) & 1);
                uint32_t bh[4];
                LDSM4(bh[0], bh[1], bh[2], bh[3], sB + swzB(r, cl));
                #pragma unroll
                for (int mi = 0; mi < 4; mi++)
                    #pragma unroll
                    for (int s2 = 0; s2 < 2; s2++)
                        MMA_BF16(acc[mi][g * 2 + s2], ah[mi], bh[2 * s2], bh[2 * s2 + 1]);
            }
        }
    }

    // ---- epilogue: column sum / sumsq over this CTA's 128 rows ----
    __syncthreads();
    float* ssum = (float*)smem;         // [256]
    float* qsum = ssum + 256;           // [256]
    ssum[tid] = 0.f; qsum[tid] = 0.f;
    __syncthreads();

    #pragma unroll
    for (int n8 = 0; n8 < 8; n8++) {
        float s0 = 0.f, q0 = 0.f, s1 = 0.f, q1 = 0.f;
        #pragma unroll
        for (int mi = 0; mi < 4; mi++) {
            float a0 = acc[mi][n8][0], a1 = acc[mi][n8][1];
            float a2 = acc[mi][n8][2], a3 = acc[mi][n8][3];
            s0 += a0 + a2; q0 += a0 * a0 + a2 * a2;
            s1 += a1 + a3; q1 += a1 * a1 + a3 * a3;
        }
        #pragma unroll
        for (int off = 4; off < 32; off <<= 1) {
            s0 += __shfl_down_sync(0xffffffffu, s0, off);
            q0 += __shfl_down_sync(0xffffffffu, q0, off);
            s1 += __shfl_down_sync(0xffffffffu, s1, off);
            q1 += __shfl_down_sync(0xffffffffu, q1, off);
        }
        if (lane < 4) {
            int col = wn * 64 + n8 * 8 + lane * 2;
            atomicAdd(&ssum[col], s0);     atomicAdd(&qsum[col], q0);
            atomicAdd(&ssum[col + 1], s1); atomicAdd(&qsum[col + 1], q1);
        }
    }
    __syncthreads();
    g_psum[blockIdx.x * DD + tid] = ssum[tid];
    g_psq [blockIdx.x * DD + tid] = qsum[tid];

    #undef LDG_A
    #undef STS_A
    #undef CP_B
}

// =====================================================================
// Kernel: BN statistics. 8 blocks x 256 threads; block b handles 32
// columns; 8 groups of 32 partials tree-reduced. Block 0 also zeros
// the per-task accumulators.
// =====================================================================
__global__ void __launch_bounds__(256) k_stats()
{
    __shared__ float ss[8][32], qq[8][32];
    const int t = threadIdx.x;
    const int col = blockIdx.x * 32 + (t & 31);
    const int grp = t >> 5;             // 0..7

    float s = 0.f, q = 0.f;
    #pragma unroll 8
    for (int b2 = grp * 32; b2 < grp * 32 + 32; b2++) {
        s += g_psum[b2 * DD + col];
        q += g_psq[b2 * DD + col];
    }
    ss[grp][t & 31] = s; qq[grp][t & 31] = q;
    if (blockIdx.x == 0 && t < 64) { g_pe[t] = 0.f; g_ne[t] = 0.f; }
    __syncthreads();
    if (t < 32) {
        float S = 0.f, Q = 0.f;
        #pragma unroll
        for (int g2 = 0; g2 < 8; g2++) { S += ss[g2][t]; Q += qq[g2][t]; }
        float mu  = S * (1.0f / 32768.0f);
        float var = Q * (1.0f / 32768.0f) - mu * mu;
        g_mu[blockIdx.x * 32 + t]   = mu;
        g_istd[blockIdx.x * 32 + t] = 1.0f / sqrtf(var + 1e-5f);
    }
}

// =====================================================================
// Kernel: normalize. 48 blocks x 128 threads.
//   blocks [0,32): BN/ReLU/L2-normalize 4 selected rows each -> g_nf
//   blocks [32,48): memory-bank inverse norms (32 rows each)
// =====================================================================
__global__ void __launch_bounds__(128) k_norm(const float* __restrict__ gamma,
                                              const float* __restrict__ beta,
                                              const float* __restrict__ mpos,
                                              const float* __restrict__ mneg)
{
    const int t = threadIdx.x;
    const int warp = t >> 5, lane = t & 31;
    const int blk = blockIdx.x;

    if (blk < 32) {
        const int sr = blk * 4 + warp;
        float v[8]; float ss = 0.f;
        #pragma unroll
        for (int k = 0; k < 8; k++) {
            int d = lane + 32 * k;
            float z = 0.f;
            #pragma unroll
            for (int c = 0; c < ZKC; c++) z += g_zpart[c][(size_t)sr * DD + d];
            float x = (z - g_mu[d]) * g_istd[d] * gamma[d] + beta[d];
            x = fmaxf(x, 0.f);
            v[k] = x; ss += x * x;
        }
        #pragma unroll
        for (int o = 16; o; o >>= 1) ss += __shfl_xor_sync(0xffffffffu, ss, o);
        float inv = 1.0f / (sqrtf(ss) + 1e-12f);
        #pragma unroll
        for (int k = 0; k < 8; k++) g_nf[sr * DD + lane + 32 * k] = v[k] * inv;
    } else {
        const int idx = blk - 32;           // 0..15
        const int bank = idx >> 3;          // 0..1
        const int r0 = (idx & 7) * 32;
        const float* m = bank ? mneg : mpos;
        for (int r = r0 + warp; r < r0 + 32; r += 4) {
            const float* mr = m + (size_t)r * DD;
            float ss = 0.f;
            #pragma unroll
            for (int k = 0; k < 8; k++) { float x = mr[lane + 32 * k]; ss += x * x; }
            #pragma unroll
            for (int o = 16; o; o >>= 1) ss += __shfl_xor_sync(0xffffffffu, ss, o);
            if (lane == 0) g_mn[bank * NMEM + r] = 1.0f / (sqrtf(ss) + 1e-12f);
        }
    }
}

// =====================================================================
// Kernel: InfoNCE partials, 256 blocks = 64 tasks x 4 j-chunks.
// =====================================================================
__global__ void k_nce(const float* __restrict__ mpos,
                      const float* __restrict__ mneg)
{
    const int task  = blockIdx.x >> 2;
    const int chunk = blockIdx.x & 3;
    const int loss = task >> 4;
    const int a    = task & 15;
    const int qslot = (loss & 1) ? (NS + a) : a;

    __shared__ float sq[DD];
    __shared__ float spe[8], sne[8];

    const int t = threadIdx.x;           // 256 threads
    const int warp = t >> 5, lane = t & 31;

    sq[t] = g_nf[qslot * DD + t];
    __syncthreads();

    float pe = 0.f, ne = 0.f;
    float ql[8];
    #pragma unroll
    for (int k = 0; k < 8; k++) ql[k] = sq[lane + 32 * k];

    if (loss < 2) {
        const int posbase = (loss == 0) ? 0 : NS;
        const int negbase = NS - posbase;
        const int j0 = chunk * 16;
        for (int j = j0 + warp; j < j0 + 16; j += 8) {
            const float* p = g_nf + (size_t)(posbase + j) * DD;
            float d = 0.f;
            #pragma unroll
            for (int k = 0; k < 8; k++) d += ql[k] * p[lane + 32 * k];
            #pragma unroll
            for (int o = 16; o; o >>= 1) d += __shfl_xor_sync(0xffffffffu, d, o);
            pe += expf(d * 10.0f) * g_sel_valid[posbase + j];

            const float* n2 = g_nf + (size_t)(negbase + j) * DD;
            float dn = 0.f;
            #pragma unroll
            for (int k = 0; k < 8; k++) dn += ql[k] * n2[lane + 32 * k];
            #pragma unroll
            for (int o = 16; o; o >>= 1) dn += __shfl_xor_sync(0xffffffffu, dn, o);
            ne += expf(dn * 10.0f) * g_sel_valid[negbase + j];
        }
    } else {
        const float* pb = (loss == 2) ? mpos : mneg;
        const float* nb = (loss == 2) ? mneg : mpos;
        const int pno = (loss == 2) ? 0 : NMEM;
        const int j0 = chunk * 64;
        for (int j = j0 + warp; j < j0 + 64; j += 8) {
            const float* p = pb + (size_t)j * DD;
            float d = 0.f;
            #pragma unroll
            for (int k = 0; k < 8; k++) d += ql[k] * p[lane + 32 * k];
            #pragma unroll
            for (int o = 16; o; o >>= 1) d += __shfl_xor_sync(0xffffffffu, d, o);
            pe += expf(d * g_mn[pno + j] * 10.0f);

            const float* n2 = nb + (size_t)j * DD;
            float dn = 0.f;
            #pragma unroll
            for (int k = 0; k < 8; k++) dn += ql[k] * n2[lane + 32 * k];
            #pragma unroll
            for (int o = 16; o; o >>= 1) dn += __shfl_xor_sync(0xffffffffu, dn, o);
            ne += expf(dn * g_mn[(pno ^ NMEM) + j] * 10.0f);
        }
    }

    if (lane == 0) { spe[warp] = pe; sne[warp] = ne; }
    __syncthreads();
    if (t == 0) {
        float P = 0.f, N = 0.f;
        #pragma unroll
        for (int w = 0; w < 8; w++) { P += spe[w]; N += sne[w]; }
        atomicAdd(&g_pe[task], P);
        atomicAdd(&g_ne[task], N);
    }
}

// =====================================================================
// Kernel: final losses + scalar output (1 block, 64 threads)
// =====================================================================
__global__ void k_out(float* __restrict__ out)
{
    __shared__ float sw2[2];
    const int t = threadIdx.x;          // 64
    const int loss = t >> 4, a = t & 15;
    const int qslot = (loss & 1) ? (NS + a) : a;

    float P = g_pe[t], N = g_ne[t];
    float lv = -logf(P / (P + N + 1e-8f) + 1e-8f) * g_sel_valid[qslot];

    #pragma unroll
    for (int o = 16; o; o >>= 1) lv += __shfl_down_sync(0xffffffffu, lv, o);
    if ((t & 31) == 0) sw2[t >> 5] = lv;
    __syncthreads();
    if (t == 0) {
        float total = sw2[0] + sw2[1];
        float n = 0.f;
        #pragma unroll
        for (int i = 0; i < 16; i++) n += g_sel_valid[i] + g_sel_valid[NS + i];
        n = fmaxf(n, 1.0f);
        out[0] = total / n;
    }
}

// =====================================================================
extern "C" void kernel_launch(void* const* d_in, const int* in_sizes, int n_in,
                              void* d_out, int out_size)
{
    const float* features = (const float*)d_in[0];
    const float* pred_ori = (const float*)d_in[1];
    const float* pred_aug = (const float*)d_in[2];
    const float* unc      = (const float*)d_in[3];
    const int*   labels   = (const int*)  d_in[4];
    const float* conv_w   = (const float*)d_in[5];
    // d_in[6] = conv_b: cancels exactly in BatchNorm -> unused
    const float* gamma    = (const float*)d_in[7];
    const float* beta     = (const float*)d_in[8];
    const float* mpos     = (const float*)d_in[9];
    const float* mneg     = (const float*)d_in[10];

    cudaFuncSetAttribute(k_mma, cudaFuncAttributeMaxDynamicSharedMemorySize, SM_MMA);

    // Single stream (multi-stream fork-join breaks the harness's graph
    // capture — learned R11). k_mma is the 4th launch (ncu -s5-c1).
    k_select<<<2, 1024>>>(pred_ori, pred_aug, unc, labels);
    k_wconv<<<512, 256>>>(conv_w);
    k_zsel<<<256, 256>>>(features, conv_w);
    k_mma<<<256, 256, SM_MMA>>>(features);
    k_stats<<<8, 256>>>();
    k_norm<<<48, 128>>>(gamma, beta, mpos, mneg);
    k_nce<<<256, 256>>>(mpos, mneg);
    k_out<<<1, 64>>>((float*)d_out);
}

// round 14
// speedup vs baseline: 3.1801x; 1.5275x over previous
#include <cuda_runtime.h>
#include <cuda_bf16.h>
#include <cstdint>
#include <math.h>

// Problem constants (fixed by setup_inputs)
#define NPIX 32768      // B*H*W = 8*64*64
#define PP   4096       // H*W
#define CC   2048       // channels (GEMM K)
#define DD   256        // projection dim (GEMM N)
#define NMEM 256        // memory bank rows
#define NS   64         // NUM_SAMPLES

// GEMM tiling (single-pass bf16: A_bf16 * W_bf16, stats-only consumer)
#define BK     32                  // K per stage
#define KT     (CC / BK)           // 64 k-iterations
#define STG_A  0                   // bf16 A [32 k][128 m] = 8KB
#define STG_B  8192                // bf16 B [256 n][32 k] = 16KB
#define STGB   24576
#define SM_MMA (3 * STGB)          // 73728 dynamic smem

#define ZKC    8                   // zsel k-chunks (256 channels each) — R8 measured config

typedef unsigned long long ull;

// ---------------- device scratch (static: no allocations allowed) ----------
__device__ __align__(16) __nv_bfloat16 g_bh[(size_t)DD * CC];     // W bf16, [n=d][k=c]
__device__ float g_psum[256 * DD];              // per-CTA column sums
__device__ float g_psq[256 * DD];               // per-CTA column sumsq
__device__ float g_mu[DD], g_istd[DD];          // BN stats
__device__ int   g_sel_idx[128];                // fg[0..63], bg[64..127]
__device__ float g_sel_valid[128];
__device__ float g_zpart[ZKC][128 * DD];        // per-kchunk partial z at selected rows
__device__ float g_nf[128 * DD];                // normalized selected features
__device__ float g_mn[2 * NMEM];                // memory-bank inverse norms
__device__ float g_pe[64], g_ne[64];            // per-task exp sums

// ---------------- PTX helpers (sm_100-base legal) ----------------
__device__ __forceinline__ uint32_t smem_u32(const void* p) {
    uint32_t a;
    asm("{ .reg .u64 t; cvta.to.shared.u64 t, %1; cvt.u32.u64 %0, t; }"
        : "=r"(a) : "l"(p));
    return a;
}

#define CP16(dst, src) \
    asm volatile("{ .reg .u64 p; cvta.to.global.u64 p, %1; " \
                 "cp.async.cg.shared.global [%0], [p], 16; }" \
                 :: "r"(dst), "l"(src))

#define CP_COMMIT() asm volatile("cp.async.commit_group;" ::: "memory")

#define LDSM4(r0, r1, r2, r3, addr) \
    asm volatile("ldmatrix.sync.aligned.m8n8.x4.shared.b16 {%0,%1,%2,%3}, [%4];" \
                 : "=r"(r0), "=r"(r1), "=r"(r2), "=r"(r3) : "r"(addr))

#define LDSM4T(r0, r1, r2, r3, addr) \
    asm volatile("ldmatrix.sync.aligned.m8n8.x4.trans.shared.b16 {%0,%1,%2,%3}, [%4];" \
                 : "=r"(r0), "=r"(r1), "=r"(r2), "=r"(r3) : "r"(addr))

#define MMA_BF16(c, a, b0, b1) \
    asm volatile("mma.sync.aligned.m16n8k16.row.col.f32.bf16.bf16.f32 " \
                 "{%0,%1,%2,%3}, {%4,%5,%6,%7}, {%8,%9}, {%0,%1,%2,%3};" \
                 : "+f"((c)[0]), "+f"((c)[1]), "+f"((c)[2]), "+f"((c)[3]) \
                 : "r"((a)[0]), "r"((a)[1]), "r"((a)[2]), "r"((a)[3]), \
                   "r"(b0), "r"(b1))

// B-tile swizzle (rows of 64B, 16B chunks c 0..3) — proven in R4
__device__ __forceinline__ uint32_t swzB(int r, int c) {
    return (uint32_t)(r * 64 + 16 * (c ^ ((r >> 1) & 3)));
}
// A-tile swizzle: [k rows][128 m bf16 = 256B = 16 chunks]
__device__ __forceinline__ uint32_t swzA(int k, int mc) {
    return (uint32_t)(k * 256 + 16 * (mc ^ (k & 15)));
}

// =====================================================================
// Kernel: hard-sample mining. block 0 -> fg (label==1), block 1 -> bg.
// Iterative block-argmax (64 rounds) replicating jax.lax.top_k exactly.
// =====================================================================
__global__ void k_select(const float* __restrict__ pred_ori,
                         const float* __restrict__ pred_aug,
                         const float* __restrict__ unc,
                         const int*   __restrict__ labels)
{
    const int cls = blockIdx.x;          // 0: fg, 1: bg
    const int tid = threadIdx.x;         // 1024 threads
    const int want = cls ? 0 : 1;

    float sc[32];
    #pragma unroll
    for (int i = 0; i < 32; i++) {
        int n = tid + (i << 10);
        int b = n >> 12, p = n & 4095;
        const float* po = pred_ori + (size_t)b * 2 * PP + p;
        const float* pa = pred_aug + (size_t)b * 2 * PP + p;
        int io = po[PP] > po[0];
        int ia = pa[PP] > pa[0];
        float u = unc[n];
        bool ok = (io == ia) && (u > 0.5f) && (labels[n] == want);
        sc[i] = ok ? u : -1e9f;
    }

    float bv = -INFINITY; int bi = -1;
    #pragma unroll
    for (int i = 0; i < 32; i++) {
        int n = tid + (i << 10);
        if (sc[i] > bv || (sc[i] == bv && n < bi)) { bv = sc[i]; bi = n; }
    }

    __shared__ float wv[32];
    __shared__ int   wi[32];
    __shared__ int   winner;

    for (int it = 0; it < NS; it++) {
        float v = bv; int ix = bi;
        #pragma unroll
        for (int o = 16; o; o >>= 1) {
            float ov = __shfl_down_sync(0xffffffffu, v, o);
            int   oi = __shfl_down_sync(0xffffffffu, ix, o);
            if (ov > v || (ov == v && oi < ix)) { v = ov; ix = oi; }
        }
        if ((tid & 31) == 0) { wv[tid >> 5] = v; wi[tid >> 5] = ix; }
        __syncthreads();
        if (tid < 32) {
            v = wv[tid]; ix = wi[tid];
            #pragma unroll
            for (int o = 16; o; o >>= 1) {
                float ov = __shfl_down_sync(0xffffffffu, v, o);
                int   oi = __shfl_down_sync(0xffffffffu, ix, o);
                if (ov > v || (ov == v && oi < ix)) { v = ov; ix = oi; }
            }
            if (tid == 0) {
                winner = ix;
                g_sel_idx[cls * NS + it]   = ix;
                g_sel_valid[cls * NS + it] = (v > -5e8f) ? 1.0f : 0.0f;
            }
        }
        __syncthreads();
        int wn = winner;
        if ((wn & 1023) == tid) {
            sc[wn >> 10] = -INFINITY;
            bv = -INFINITY; bi = -1;
            #pragma unroll
            for (int i = 0; i < 32; i++) {
                int n = tid + (i << 10);
                if (sc[i] > bv || (sc[i] == bv && n < bi)) { bv = sc[i]; bi = n; }
            }
        }
        __syncthreads();
    }
}

// =====================================================================
// Kernel: W -> bf16, transposed to [n=d][k=c] (K-major).
// conv_b omitted: cancels exactly in BatchNorm.
// =====================================================================
__global__ void __launch_bounds__(256) k_wconv(const float* __restrict__ Wt)
{
    __shared__ float s[32][33];
    const int bid = blockIdx.x;         // 512 blocks
    const int tid = threadIdx.x;
    const int li = tid >> 5;            // 0..7
    const int lj = tid & 31;
    const int d0 = (bid & 7) << 5, c0 = (bid >> 3) << 5;

    #pragma unroll
    for (int i4 = 0; i4 < 4; i4++) {
        int i = li + i4 * 8;
        s[i][lj] = Wt[(size_t)(c0 + i) * DD + d0 + lj];
    }
    __syncthreads();
    #pragma unroll
    for (int i4 = 0; i4 < 4; i4++) {
        int r = li + i4 * 8;            // d-local
        g_bh[(size_t)(d0 + r) * CC + c0 + lj] = __float2bfloat16(s[lj][r]);
    }
}

// =====================================================================
// Kernel: exact fp32 z partials for the 128 selected rows.
// 256 blocks = 32 row-groups (4 rows) x 8 k-chunks — R8 measured config.
// =====================================================================
__global__ void __launch_bounds__(256) k_zsel(const float* __restrict__ F,
                                              const float* __restrict__ Wt)
{
    __shared__ float f[4][256];
    const int rg  = blockIdx.x >> 3;    // 0..31
    const int kc  = blockIdx.x & 7;     // 0..7
    const int kc0 = kc << 8;
    const int t = threadIdx.x;          // 256

    int bs[4], ps[4];
    #pragma unroll
    for (int r = 0; r < 4; r++) {
        int m = g_sel_idx[rg * 4 + r];
        bs[r] = m >> 12; ps[r] = m & 4095;
    }

    #pragma unroll
    for (int i = 0; i < 4; i++) {
        int idx = t + (i << 8);
        int r = idx >> 8, k = idx & 255;
        f[r][k] = F[(size_t)bs[r] * CC * PP + (size_t)(kc0 + k) * PP + ps[r]];
    }
    __syncthreads();

    float a0 = 0.f, a1 = 0.f, a2 = 0.f, a3 = 0.f;
    #pragma unroll 8
    for (int k = 0; k < 256; k++) {
        float w = Wt[(size_t)(kc0 + k) * DD + t];
        a0 += f[0][k] * w;
        a1 += f[1][k] * w;
        a2 += f[2][k] * w;
        a3 += f[3][k] * w;
    }
    float* dst = g_zpart[kc] + (size_t)(rg * 4) * DD + t;
    dst[0 * DD] = a0;
    dst[1 * DD] = a1;
    dst[2 * DD] = a2;
    dst[3 * DD] = a3;
}

// =====================================================================
// Kernel: fused bf16 stats-GEMM. Measured R10: 130.7us = mma.sync
// ceiling. UNCHANGED.
// =====================================================================
__global__ void __launch_bounds__(256, 1) k_mma(const float* __restrict__ F)
{
    extern __shared__ char smem[];
    const uint32_t sb = smem_u32(smem);
    const int tid = threadIdx.x;
    const int wid = tid >> 5, lane = tid & 31;
    const int wm = wid & 1, wn = wid >> 1;     // 2m x 4n
    const int m0 = blockIdx.x << 7;
    const int b = m0 >> 12, p0 = m0 & 4095;
    const float* Fb = F + (size_t)b * CC * PP + p0;

    float acc[4][8][4];
    #pragma unroll
    for (int mi = 0; mi < 4; mi++)
        #pragma unroll
        for (int n8 = 0; n8 < 8; n8++)
            #pragma unroll
            for (int q = 0; q < 4; q++) acc[mi][n8][q] = 0.f;

    float4 ar[4];
    const int arow[4] = { tid >> 5, (tid >> 5) + 8, (tid >> 5) + 16, (tid >> 5) + 24 };
    const int acol4 = tid & 31;

    #define LDG_A(kb) do { \
        _Pragma("unroll") \
        for (int i = 0; i < 4; i++) \
            ar[i] = *(const float4*)(Fb + (size_t)((kb) + arow[i]) * PP + acol4 * 4); \
    } while (0)

    #define STS_A(slotbase) do { \
        _Pragma("unroll") \
        for (int i = 0; i < 4; i++) { \
            __nv_bfloat162 p0b = __floats2bfloat162_rn(ar[i].x, ar[i].y); \
            __nv_bfloat162 p1b = __floats2bfloat162_rn(ar[i].z, ar[i].w); \
            uint32_t u0 = *(uint32_t*)&p0b, u1 = *(uint32_t*)&p1b; \
            ull v = (ull)u0 | ((ull)u1 << 32); \
            uint32_t dst = (slotbase) + STG_A + swzA(arow[i], acol4 >> 1) + (acol4 & 1) * 8; \
            asm volatile("st.shared.b64 [%0], %1;" :: "r"(dst), "l"(v)); \
        } \
    } while (0)

    #define CP_B(kb, slotbase) do { \
        _Pragma("unroll") \
        for (int i = 0; i < 4; i++) { \
            int idx = tid + (i << 8); \
            int r = idx >> 2, c = idx & 3; \
            const __nv_bfloat16* src = g_bh + (size_t)r * CC + (kb) + c * 8; \
            CP16((slotbase) + STG_B + swzB(r, c), src); \
        } \
    } while (0)

    // prologue
    LDG_A(0);
    CP_B(0, sb + 0 * STGB); CP_COMMIT();
    STS_A(sb + 0 * STGB);
    LDG_A(BK);
    CP_B(BK, sb + 1 * STGB); CP_COMMIT();

    for (int kt = 0; kt < KT; kt++) {
        const uint32_t slot   = sb + (kt % 3) * STGB;
        const uint32_t slotN1 = sb + ((kt + 1) % 3) * STGB;
        const uint32_t slotN2 = sb + ((kt + 2) % 3) * STGB;

        if (kt + 1 < KT) STS_A(slotN1);
        if (kt + 2 < KT) LDG_A((kt + 2) * BK);

        if (kt < KT - 1) asm volatile("cp.async.wait_group 1;" ::: "memory");
        else             asm volatile("cp.async.wait_group 0;" ::: "memory");
        __syncthreads();
        if (kt + 2 < KT) { CP_B((kt + 2) * BK, slotN2); CP_COMMIT(); }

        const uint32_t sA = slot + STG_A;
        const uint32_t sB = slot + STG_B;

        #pragma unroll
        for (int k16 = 0; k16 < 2; k16++) {
            const int kc = k16 * 2;
            const int k0 = k16 * 16;
            uint32_t ah[4][4];
            #pragma unroll
            for (int mi = 0; mi < 4; mi++) {
                int krow = k0 + (lane & 7) + ((lane >> 4) << 3);
                int mc = wm * 8 + mi * 2 + ((lane >> 3) & 1);
                LDSM4T(ah[mi][0], ah[mi][1], ah[mi][2], ah[mi][3],
                       sA + swzA(krow, mc));
            }
            #pragma unroll
            for (int g = 0; g < 4; g++) {
                int r = wn * 64 + g * 16 + (lane & 7) + ((lane >> 4) << 3);
                int cl = kc + ((lane >> 3) & 1);
                uint32_t bh[4];
                LDSM4(bh[0], bh[1], bh[2], bh[3], sB + swzB(r, cl));
                #pragma unroll
                for (int mi = 0; mi < 4; mi++)
                    #pragma unroll
                    for (int s2 = 0; s2 < 2; s2++)
                        MMA_BF16(acc[mi][g * 2 + s2], ah[mi], bh[2 * s2], bh[2 * s2 + 1]);
            }
        }
    }

    // ---- epilogue: column sum / sumsq over this CTA's 128 rows ----
    __syncthreads();
    float* ssum = (float*)smem;         // [256]
    float* qsum = ssum + 256;           // [256]
    ssum[tid] = 0.f; qsum[tid] = 0.f;
    __syncthreads();

    #pragma unroll
    for (int n8 = 0; n8 < 8; n8++) {
        float s0 = 0.f, q0 = 0.f, s1 = 0.f, q1 = 0.f;
        #pragma unroll
        for (int mi = 0; mi < 4; mi++) {
            float a0 = acc[mi][n8][0], a1 = acc[mi][n8][1];
            float a2 = acc[mi][n8][2], a3 = acc[mi][n8][3];
            s0 += a0 + a2; q0 += a0 * a0 + a2 * a2;
            s1 += a1 + a3; q1 += a1 * a1 + a3 * a3;
        }
        #pragma unroll
        for (int off = 4; off < 32; off <<= 1) {
            s0 += __shfl_down_sync(0xffffffffu, s0, off);
            q0 += __shfl_down_sync(0xffffffffu, q0, off);
            s1 += __shfl_down_sync(0xffffffffu, s1, off);
            q1 += __shfl_down_sync(0xffffffffu, q1, off);
        }
        if (lane < 4) {
            int col = wn * 64 + n8 * 8 + lane * 2;
            atomicAdd(&ssum[col], s0);     atomicAdd(&qsum[col], q0);
            atomicAdd(&ssum[col + 1], s1); atomicAdd(&qsum[col + 1], q1);
        }
    }
    __syncthreads();
    g_psum[blockIdx.x * DD + tid] = ssum[tid];
    g_psq [blockIdx.x * DD + tid] = qsum[tid];

    #undef LDG_A
    #undef STS_A
    #undef CP_B
}

// =====================================================================
// Kernel: BN statistics. 8 blocks x 256 threads.
// =====================================================================
__global__ void __launch_bounds__(256) k_stats()
{
    __shared__ float ss[8][32], qq[8][32];
    const int t = threadIdx.x;
    const int col = blockIdx.x * 32 + (t & 31);
    const int grp = t >> 5;             // 0..7

    float s = 0.f, q = 0.f;
    #pragma unroll 8
    for (int b2 = grp * 32; b2 < grp * 32 + 32; b2++) {
        s += g_psum[b2 * DD + col];
        q += g_psq[b2 * DD + col];
    }
    ss[grp][t & 31] = s; qq[grp][t & 31] = q;
    if (blockIdx.x == 0 && t < 64) { g_pe[t] = 0.f; g_ne[t] = 0.f; }
    __syncthreads();
    if (t < 32) {
        float S = 0.f, Q = 0.f;
        #pragma unroll
        for (int g2 = 0; g2 < 8; g2++) { S += ss[g2][t]; Q += qq[g2][t]; }
        float mu  = S * (1.0f / 32768.0f);
        float var = Q * (1.0f / 32768.0f) - mu * mu;
        g_mu[blockIdx.x * 32 + t]   = mu;
        g_istd[blockIdx.x * 32 + t] = 1.0f / sqrtf(var + 1e-5f);
    }
}

// =====================================================================
// Kernel: normalize. 48 blocks x 128 threads.
// =====================================================================
__global__ void __launch_bounds__(128) k_norm(const float* __restrict__ gamma,
                                              const float* __restrict__ beta,
                                              const float* __restrict__ mpos,
                                              const float* __restrict__ mneg)
{
    const int t = threadIdx.x;
    const int warp = t >> 5, lane = t & 31;
    const int blk = blockIdx.x;

    if (blk < 32) {
        const int sr = blk * 4 + warp;
        float v[8]; float ss = 0.f;
        #pragma unroll
        for (int k = 0; k < 8; k++) {
            int d = lane + 32 * k;
            float z = 0.f;
            #pragma unroll
            for (int c = 0; c < ZKC; c++) z += g_zpart[c][(size_t)sr * DD + d];
            float x = (z - g_mu[d]) * g_istd[d] * gamma[d] + beta[d];
            x = fmaxf(x, 0.f);
            v[k] = x; ss += x * x;
        }
        #pragma unroll
        for (int o = 16; o; o >>= 1) ss += __shfl_xor_sync(0xffffffffu, ss, o);
        float inv = 1.0f / (sqrtf(ss) + 1e-12f);
        #pragma unroll
        for (int k = 0; k < 8; k++) g_nf[sr * DD + lane + 32 * k] = v[k] * inv;
    } else {
        const int idx = blk - 32;           // 0..15
        const int bank = idx >> 3;          // 0..1
        const int r0 = (idx & 7) * 32;
        const float* m = bank ? mneg : mpos;
        for (int r = r0 + warp; r < r0 + 32; r += 4) {
            const float* mr = m + (size_t)r * DD;
            float ss = 0.f;
            #pragma unroll
            for (int k = 0; k < 8; k++) { float x = mr[lane + 32 * k]; ss += x * x; }
            #pragma unroll
            for (int o = 16; o; o >>= 1) ss += __shfl_xor_sync(0xffffffffu, ss, o);
            if (lane == 0) g_mn[bank * NMEM + r] = 1.0f / (sqrtf(ss) + 1e-12f);
        }
    }
}

// =====================================================================
// Kernel: InfoNCE partials, 256 blocks = 64 tasks x 4 j-chunks.
// =====================================================================
__global__ void k_nce(const float* __restrict__ mpos,
                      const float* __restrict__ mneg)
{
    const int task  = blockIdx.x >> 2;
    const int chunk = blockIdx.x & 3;
    const int loss = task >> 4;
    const int a    = task & 15;
    const int qslot = (loss & 1) ? (NS + a) : a;

    __shared__ float sq[DD];
    __shared__ float spe[8], sne[8];

    const int t = threadIdx.x;           // 256 threads
    const int warp = t >> 5, lane = t & 31;

    sq[t] = g_nf[qslot * DD + t];
    __syncthreads();

    float pe = 0.f, ne = 0.f;
    float ql[8];
    #pragma unroll
    for (int k = 0; k < 8; k++) ql[k] = sq[lane + 32 * k];

    if (loss < 2) {
        const int posbase = (loss == 0) ? 0 : NS;
        const int negbase = NS - posbase;
        const int j0 = chunk * 16;
        for (int j = j0 + warp; j < j0 + 16; j += 8) {
            const float* p = g_nf + (size_t)(posbase + j) * DD;
            float d = 0.f;
            #pragma unroll
            for (int k = 0; k < 8; k++) d += ql[k] * p[lane + 32 * k];
            #pragma unroll
            for (int o = 16; o; o >>= 1) d += __shfl_xor_sync(0xffffffffu, d, o);
            pe += expf(d * 10.0f) * g_sel_valid[posbase + j];

            const float* n2 = g_nf + (size_t)(negbase + j) * DD;
            float dn = 0.f;
            #pragma unroll
            for (int k = 0; k < 8; k++) dn += ql[k] * n2[lane + 32 * k];
            #pragma unroll
            for (int o = 16; o; o >>= 1) dn += __shfl_xor_sync(0xffffffffu, dn, o);
            ne += expf(dn * 10.0f) * g_sel_valid[negbase + j];
        }
    } else {
        const float* pb = (loss == 2) ? mpos : mneg;
        const float* nb = (loss == 2) ? mneg : mpos;
        const int pno = (loss == 2) ? 0 : NMEM;
        const int j0 = chunk * 64;
        for (int j = j0 + warp; j < j0 + 64; j += 8) {
            const float* p = pb + (size_t)j * DD;
            float d = 0.f;
            #pragma unroll
            for (int k = 0; k < 8; k++) d += ql[k] * p[lane + 32 * k];
            #pragma unroll
            for (int o = 16; o; o >>= 1) d += __shfl_xor_sync(0xffffffffu, d, o);
            pe += expf(d * g_mn[pno + j] * 10.0f);

            const float* n2 = nb + (size_t)j * DD;
            float dn = 0.f;
            #pragma unroll
            for (int k = 0; k < 8; k++) dn += ql[k] * n2[lane + 32 * k];
            #pragma unroll
            for (int o = 16; o; o >>= 1) dn += __shfl_xor_sync(0xffffffffu, dn, o);
            ne += expf(dn * g_mn[(pno ^ NMEM) + j] * 10.0f);
        }
    }

    if (lane == 0) { spe[warp] = pe; sne[warp] = ne; }
    __syncthreads();
    if (t == 0) {
        float P = 0.f, N = 0.f;
        #pragma unroll
        for (int w = 0; w < 8; w++) { P += spe[w]; N += sne[w]; }
        atomicAdd(&g_pe[task], P);
        atomicAdd(&g_ne[task], N);
    }
}

// =====================================================================
// Kernel: final losses + scalar output (1 block, 64 threads)
// =====================================================================
__global__ void k_out(float* __restrict__ out)
{
    __shared__ float sw2[2];
    const int t = threadIdx.x;          // 64
    const int loss = t >> 4, a = t & 15;
    const int qslot = (loss & 1) ? (NS + a) : a;

    float P = g_pe[t], N = g_ne[t];
    float lv = -logf(P / (P + N + 1e-8f) + 1e-8f) * g_sel_valid[qslot];

    #pragma unroll
    for (int o = 16; o; o >>= 1) lv += __shfl_down_sync(0xffffffffu, lv, o);
    if ((t & 31) == 0) sw2[t >> 5] = lv;
    __syncthreads();
    if (t == 0) {
        float total = sw2[0] + sw2[1];
        float n = 0.f;
        #pragma unroll
        for (int i = 0; i < 16; i++) n += g_sel_valid[i] + g_sel_valid[NS + i];
        n = fmaxf(n, 1.0f);
        out[0] = total / n;
    }
}

// =====================================================================
extern "C" void kernel_launch(void* const* d_in, const int* in_sizes, int n_in,
                              void* d_out, int out_size)
{
    const float* features = (const float*)d_in[0];
    const float* pred_ori = (const float*)d_in[1];
    const float* pred_aug = (const float*)d_in[2];
    const float* unc      = (const float*)d_in[3];
    const int*   labels   = (const int*)  d_in[4];
    const float* conv_w   = (const float*)d_in[5];
    // d_in[6] = conv_b: cancels exactly in BatchNorm -> unused
    const float* gamma    = (const float*)d_in[7];
    const float* beta     = (const float*)d_in[8];
    const float* mpos     = (const float*)d_in[9];
    const float* mneg     = (const float*)d_in[10];

    cudaFuncSetAttribute(k_mma, cudaFuncAttributeMaxDynamicSharedMemorySize, SM_MMA);

    // Fork-join overlap (supported capture pattern: fork/join via events
    // against the origin stream):
    //   s2: select -> zsel              (~63us, independent of W path)
    //   0 : wconv -> mma -> stats       (critical path, ~144us)
    //   join, then norm -> nce -> out.
    // The two branches write disjoint device globals; all consumers run
    // after the join. Events are timing-disabled (capture requirement).
    cudaStream_t s2;
    cudaEvent_t evF, evJ;
    cudaStreamCreate(&s2);
    cudaEventCreateWithFlags(&evF, cudaEventDisableTiming);
    cudaEventCreateWithFlags(&evJ, cudaEventDisableTiming);

    cudaEventRecord(evF, 0);
    cudaStreamWaitEvent(s2, evF, 0);
    k_select<<<2, 1024, 0, s2>>>(pred_ori, pred_aug, unc, labels);
    k_zsel<<<256, 256, 0, s2>>>(features, conv_w);
    cudaEventRecord(evJ, s2);

    k_wconv<<<512, 256>>>(conv_w);
    k_mma<<<256, 256, SM_MMA>>>(features);
    k_stats<<<8, 256>>>();

    cudaStreamWaitEvent(0, evJ, 0);
    k_norm<<<48, 128>>>(gamma, beta, mpos, mneg);
    k_nce<<<256, 256>>>(mpos, mneg);
    k_out<<<1, 64>>>((float*)d_out);
}